// round 11
// baseline (speedup 1.0000x reference)
#include <cuda_runtime.h>
#include <cuda_bf16.h>
#include <cstdint>

#define CH 64
#define TT 2048
#define NB 64
#define BM 128            // queries per CTA
#define BN 128            // keys per iteration
#define NTILES (TT / BN)  // 16
#define NTH 256           // 8 warps
#define NWS 8

// tcgen05 only exists under arch-accelerated targets (sm_103a / sm_100a).
#if defined(__CUDA_ARCH__) && \
    ((__CUDA_ARCH__ == 1030 && defined(__CUDA_ARCH_FEAT_SM103_ALL)) || \
     (__CUDA_ARCH__ == 1000 && defined(__CUDA_ARCH_FEAT_SM100_ALL)))
#define TC_PATH 1
#else
#define TC_PATH 0
#endif

// ---------------- scratch: pre-split, pre-swizzled bf16 tiles ----------------
// qt/kt: [b][t(2048)][32 words] rows of 128B (64 ch bf16), SW128-swizzled.
// v:     [b][tile64(32)][c(64)][32 words] rows of 128B (64 keys bf16), swizzled.
__device__ uint32_t g_qt_h[(size_t)NB * 2048 * 32];
__device__ uint32_t g_qt_l[(size_t)NB * 2048 * 32];
__device__ uint32_t g_kt_h[(size_t)NB * 2048 * 32];
__device__ uint32_t g_kt_l[(size_t)NB * 2048 * 32];
__device__ uint32_t g_v_h[(size_t)NB * 32 * 64 * 32];
__device__ uint32_t g_v_l[(size_t)NB * 32 * 64 * 32];

// fast 2-way bf16 split
__device__ __forceinline__ void split2(float f0, float f1, uint32_t& hp, uint32_t& lp) {
    asm("cvt.rn.bf16x2.f32 %0, %1, %2;" : "=r"(hp) : "f"(f1), "f"(f0));
    const float h0 = __uint_as_float(hp << 16);
    const float h1 = __uint_as_float(hp & 0xFFFF0000u);
    asm("cvt.rn.bf16x2.f32 %0, %1, %2;" : "=r"(lp) : "f"(f1 - h1), "f"(f0 - h0));
}

// ---------------- prep kernel: fp32 -> split bf16 tiles (runs once) ----------
__global__ void prep_kernel(const float* __restrict__ qkv) {
    __shared__ float sT[64 * 65];
    const int b = blockIdx.y, tile = blockIdx.x, t0 = tile * 64;
    const int tid = threadIdx.x;
    const float* qp = qkv + (size_t)b * 3 * CH * TT;
    const float* kp = qp + (size_t)CH * TT;
    const float* vp = qp + 2 * (size_t)CH * TT;

    for (int e = tid; e < 64 * 32; e += 256) {
        const int c = e >> 5, su = e & 31;
        const float2 f = *(const float2*)(vp + (size_t)c * TT + t0 + 2 * su);
        uint32_t hp, lp; split2(f.x, f.y, hp, lp);
        const size_t o = ((size_t)(b * 32 + tile) * 64 + c) * 32 + (su ^ ((c & 7) << 2));
        g_v_h[o] = hp; g_v_l[o] = lp;
    }
    for (int e = tid; e < 4096; e += 256) {
        const int c = e >> 6, t = e & 63;
        sT[c * 65 + t] = qp[(size_t)c * TT + t0 + t];
    }
    __syncthreads();
    for (int e = tid; e < 2048; e += 256) {
        const int r = e >> 5, un = e & 31;
        uint32_t hp, lp; split2(sT[(2 * un) * 65 + r], sT[(2 * un + 1) * 65 + r], hp, lp);
        const size_t o = ((size_t)b * 2048 + t0 + r) * 32 + (un ^ ((r & 7) << 2));
        g_qt_h[o] = hp; g_qt_l[o] = lp;
    }
    __syncthreads();
    for (int e = tid; e < 4096; e += 256) {
        const int c = e >> 6, t = e & 63;
        sT[c * 65 + t] = kp[(size_t)c * TT + t0 + t];
    }
    __syncthreads();
    for (int e = tid; e < 2048; e += 256) {
        const int r = e >> 5, un = e & 31;
        uint32_t hp, lp; split2(sT[(2 * un) * 65 + r], sT[(2 * un + 1) * 65 + r], hp, lp);
        const size_t o = ((size_t)b * 2048 + t0 + r) * 32 + (un ^ ((r & 7) << 2));
        g_kt_h[o] = hp; g_kt_l[o] = lp;
    }
}

#if TC_PATH
// ---------------- PTX helpers (sm_103a) ----------------
__device__ __forceinline__ uint32_t smem_u32(const void* p) {
    uint32_t a;
    asm("{ .reg .u64 t; cvta.to.shared.u64 t, %1; cvt.u32.u64 %0, t; }" : "=r"(a) : "l"(p));
    return a;
}
__device__ __forceinline__ uint32_t elect_one() {
    uint32_t p;
    asm volatile("{ .reg .pred p; elect.sync _|p, 0xFFFFFFFF; selp.b32 %0, 1, 0, p; }" : "=r"(p));
    return p;
}

#define MBARRIER_INIT(addr, cnt) \
    asm volatile("mbarrier.init.shared.b64 [%0], %1;" :: "r"((uint32_t)(addr)), "r"((uint32_t)(cnt)) : "memory")
#define MBARRIER_ARRIVE(addr) \
    asm volatile("mbarrier.arrive.shared.b64 _, [%0];" :: "r"((uint32_t)(addr)) : "memory")
#define MBARRIER_EXPECT_TX(addr, n) \
    asm volatile("mbarrier.arrive.expect_tx.shared.b64 _, [%0], %1;" :: "r"((uint32_t)(addr)), "r"((uint32_t)(n)) : "memory")

#define MBARRIER_WAIT_PARITY(addr, par) do {                                             \
    uint32_t _mb = (uint32_t)(addr);  uint32_t _pa = (uint32_t)(par);  uint32_t _dn;     \
    asm volatile("{ .reg .pred p; mbarrier.try_wait.parity.acquire.cta.shared::cta.b64 " \
                 "p, [%1], %2; selp.b32 %0, 1, 0, p; }"                                  \
                 : "=r"(_dn) : "r"(_mb), "r"(_pa) : "memory");                           \
    if (!_dn) {                                                                          \
        asm volatile("{ .reg .pred P1;\n"                                                \
                     "WL_%=: mbarrier.try_wait.parity.acquire.cta.shared::cta.b64 "      \
                     "P1, [%0], %1, 0x989680;\n"                                         \
                     "@P1 bra.uni WD_%=;\n bra.uni WL_%=;\nWD_%=: }"                     \
                     :: "r"(_mb), "r"(_pa) : "memory");                                  \
    } } while (0)

#define BULK_G2S(dst, src, bytes, mbar)                                                          \
    asm volatile("cp.async.bulk.shared::cluster.global.mbarrier::complete_tx::bytes "            \
                 "[%0], [%1], %2, [%3];"                                                          \
                 :: "r"((uint32_t)(dst)), "l"((unsigned long long)(uintptr_t)(src)),              \
                    "r"((uint32_t)(bytes)), "r"((uint32_t)(mbar)) : "memory")

#define TCGEN05_ALLOC(saddr, n) \
    asm volatile("tcgen05.alloc.cta_group::1.sync.aligned.shared::cta.b32 [%0], %1;" \
                 :: "r"((uint32_t)(saddr)), "r"((uint32_t)(n)) : "memory")
#define TCGEN05_DEALLOC(t, n) \
    asm volatile("tcgen05.dealloc.cta_group::1.sync.aligned.b32 %0, %1;" :: "r"(t), "r"((uint32_t)(n)))
#define TCGEN05_RELINQ() \
    asm volatile("tcgen05.relinquish_alloc_permit.cta_group::1.sync.aligned;")
#define TCGEN05_COMMIT(mb) \
    asm volatile("tcgen05.commit.cta_group::1.mbarrier::arrive::one.shared::cluster.b64 [%0];" \
                 :: "r"((uint32_t)(mb)) : "memory")
#define TCGEN05_WAIT_LD()  asm volatile("tcgen05.wait::ld.sync.aligned;" ::: "memory")
#define TCGEN05_WAIT_ST()  asm volatile("tcgen05.wait::st.sync.aligned;" ::: "memory")
#define TCGEN05_FENCE_BEFORE() asm volatile("tcgen05.fence::before_thread_sync;" ::: "memory")
#define TCGEN05_FENCE_AFTER()  asm volatile("tcgen05.fence::after_thread_sync;" ::: "memory")

#define LDTM_X32(r, a)                                                             \
    asm volatile("tcgen05.ld.sync.aligned.32x32b.x32.b32 "                          \
        "{%0,%1,%2,%3,%4,%5,%6,%7,%8,%9,%10,%11,%12,%13,%14,%15,"                  \
        "%16,%17,%18,%19,%20,%21,%22,%23,%24,%25,%26,%27,%28,%29,%30,%31}, [%32];" \
        : "=r"((r)[0]),"=r"((r)[1]),"=r"((r)[2]),"=r"((r)[3]),                      \
          "=r"((r)[4]),"=r"((r)[5]),"=r"((r)[6]),"=r"((r)[7]),                      \
          "=r"((r)[8]),"=r"((r)[9]),"=r"((r)[10]),"=r"((r)[11]),                    \
          "=r"((r)[12]),"=r"((r)[13]),"=r"((r)[14]),"=r"((r)[15]),                  \
          "=r"((r)[16]),"=r"((r)[17]),"=r"((r)[18]),"=r"((r)[19]),                  \
          "=r"((r)[20]),"=r"((r)[21]),"=r"((r)[22]),"=r"((r)[23]),                  \
          "=r"((r)[24]),"=r"((r)[25]),"=r"((r)[26]),"=r"((r)[27]),                  \
          "=r"((r)[28]),"=r"((r)[29]),"=r"((r)[30]),"=r"((r)[31])                   \
        : "r"(a))

#define STTM_X16(a, r)                                                       \
    asm volatile("tcgen05.st.sync.aligned.32x32b.x16.b32 [%0], "             \
        "{%1,%2,%3,%4,%5,%6,%7,%8,%9,%10,%11,%12,%13,%14,%15,%16};"          \
        :: "r"(a),                                                           \
           "r"((r)[0]),"r"((r)[1]),"r"((r)[2]),"r"((r)[3]),                  \
           "r"((r)[4]),"r"((r)[5]),"r"((r)[6]),"r"((r)[7]),                  \
           "r"((r)[8]),"r"((r)[9]),"r"((r)[10]),"r"((r)[11]),                \
           "r"((r)[12]),"r"((r)[13]),"r"((r)[14]),"r"((r)[15])               \
        : "memory")

static constexpr uint64_t DESC_BASE_SW128 =
    (uint64_t(2) << 61) | (uint64_t(1) << 46) | (uint64_t(64) << 32) | (uint64_t(1) << 16);
__device__ __forceinline__ uint64_t mk_desc(uint32_t a) {
    return DESC_BASE_SW128 | ((uint64_t)(a >> 4) & 0x3FFF);
}

// idesc: F32 accum, BF16 a/b, M=128; N=128 for QK, N=64 for PV
#define IDESC_QK 0x8200490u
#define IDESC_PV 0x8100490u

__device__ __forceinline__ void mma_ss(uint32_t d, uint64_t ad, uint64_t bd, uint32_t idesc, bool acc) {
    uint32_t en = acc ? 1u : 0u;
    asm volatile(
        "{ .reg .pred p; setp.ne.u32 p, %5, 0;\n"
        "tcgen05.mma.cta_group::1.kind::f16 [%0], %1, %2, %3, {%4,%4,%4,%4}, p; }"
        :: "r"(d), "l"(ad), "l"(bd), "r"(idesc), "r"(0u), "r"(en) : "memory");
}
__device__ __forceinline__ void mma_ts(uint32_t d, uint32_t at, uint64_t bd, uint32_t idesc, bool acc) {
    uint32_t en = acc ? 1u : 0u;
    asm volatile(
        "{ .reg .pred p; setp.ne.u32 p, %5, 0;\n"
        "tcgen05.mma.cta_group::1.kind::f16 [%0], [%1], %2, %3, {%4,%4,%4,%4}, p; }"
        :: "r"(d), "r"(at), "l"(bd), "r"(idesc), "r"(0u), "r"(en) : "memory");
}
#endif  // TC_PATH helpers

// ---------------- SMEM / TMEM layout (tc path) ----------------
#define SM_TPTR   0
#define MB_K0     16
#define MB_K1     24
#define MB_V0     32
#define MB_V1     40
#define MB_QK0    48
#define MB_QK1    56
#define MB_PV0    64
#define MB_PV1    72
#define MB_PR     80
#define MB_SF0    88
#define MB_SF1    96
#define SM_LSUM   128          // 8*32 floats
#define SM_QH     2048
#define SM_QL     (SM_QH + 16384)
#define SM_KST    (SM_QL + 16384)      // 2 K stages x 32KB (kh 16K | kl 16K)
#define SM_VST    (SM_KST + 65536)     // 2 V stages x 32KB (vh 16K | vl 16K)
#define SM_TOTAL  (SM_VST + 65536)     // 165888 bytes -> 1 CTA/SM

// TMEM: S0 @0 (128 cols), S1 @128, PH @256 (64), PL @320 (64), O @384 (64)
#define TM_PH 256
#define TM_PL 320
#define TM_O  384
#define TM_COLS 512

// ---------------- tensor-core attention kernel ----------------
__global__ __launch_bounds__(NTH, 1) void attn_tc(const float* __restrict__ qkv,
                                                  float* __restrict__ out) {
#if TC_PATH
    extern __shared__ char smem[];
    const uint32_t sb = smem_u32(smem);
    const int tid = threadIdx.x;
    const int wid = tid >> 5;
    const int lid = tid & 31;
    const int b = blockIdx.y;
    const int qb = blockIdx.x * BM;

    if (wid == 0) { TCGEN05_ALLOC(sb + SM_TPTR, TM_COLS); TCGEN05_RELINQ(); }
    if (tid == 0) {
        MBARRIER_INIT(sb + MB_K0, 1);  MBARRIER_INIT(sb + MB_K1, 1);
        MBARRIER_INIT(sb + MB_V0, 1);  MBARRIER_INIT(sb + MB_V1, 1);
        MBARRIER_INIT(sb + MB_QK0, 1); MBARRIER_INIT(sb + MB_QK1, 1);
        MBARRIER_INIT(sb + MB_PV0, 1); MBARRIER_INIT(sb + MB_PV1, 1);
        MBARRIER_INIT(sb + MB_PR, NWS);
        MBARRIER_INIT(sb + MB_SF0, NWS); MBARRIER_INIT(sb + MB_SF1, NWS);
    }

    // Q tile copy (pre-split scratch)
    {
        const uint4* qh = (const uint4*)(g_qt_h + ((size_t)b * 2048 + qb) * 32);
        const uint4* ql = (const uint4*)(g_qt_l + ((size_t)b * 2048 + qb) * 32);
        uint4* dh = (uint4*)(smem + SM_QH);
        uint4* dl = (uint4*)(smem + SM_QL);
        for (int e = tid; e < 1024; e += NTH) { dh[e] = qh[e]; dl[e] = ql[e]; }
    }
    asm volatile("fence.proxy.async.shared::cta;" ::: "memory");
    __syncthreads();

    uint32_t tb;
    asm volatile("ld.shared.b32 %0, [%1];" : "=r"(tb) : "r"(sb + SM_TPTR));

    const uint64_t aH = mk_desc(sb + SM_QH), aL = mk_desc(sb + SM_QL);

    // Prologue: warp2 loads K0,K1; warp3 loads V0,V1; warp0 issues QK(0).
    if (wid == 2 && elect_one()) {
        #pragma unroll
        for (int j = 0; j < 2; j++) {
            const uint32_t kst = sb + SM_KST + j * 32768;
            MBARRIER_EXPECT_TX(sb + MB_K0 + 8 * j, 32768);
            BULK_G2S(kst,         (const char*)g_kt_h + ((size_t)b * 2048 + j * 128) * 128, 16384, sb + MB_K0 + 8 * j);
            BULK_G2S(kst + 16384, (const char*)g_kt_l + ((size_t)b * 2048 + j * 128) * 128, 16384, sb + MB_K0 + 8 * j);
        }
    }
    if (wid == 3 && elect_one()) {
        #pragma unroll
        for (int j = 0; j < 2; j++) {
            const uint32_t vst = sb + SM_VST + j * 32768;
            MBARRIER_EXPECT_TX(sb + MB_V0 + 8 * j, 32768);
            BULK_G2S(vst,         (const char*)g_v_h + ((size_t)(b * 32 + 2 * j)) * 8192, 16384, sb + MB_V0 + 8 * j);
            BULK_G2S(vst + 16384, (const char*)g_v_l + ((size_t)(b * 32 + 2 * j)) * 8192, 16384, sb + MB_V0 + 8 * j);
        }
    }
    if (wid == 0 && elect_one()) {
        MBARRIER_WAIT_PARITY(sb + MB_K0, 0);
        const uint32_t kst = sb + SM_KST;
        const uint64_t kh = mk_desc(kst), kl = mk_desc(kst + 16384);
        #pragma unroll
        for (int k = 0; k < 4; k++) mma_ss(tb, aH + 2 * k, kh + 2 * k, IDESC_QK, k != 0);
        #pragma unroll
        for (int k = 0; k < 4; k++) mma_ss(tb, aH + 2 * k, kl + 2 * k, IDESC_QK, true);
        #pragma unroll
        for (int k = 0; k < 4; k++) mma_ss(tb, aL + 2 * k, kh + 2 * k, IDESC_QK, true);
        TCGEN05_COMMIT(sb + MB_QK0);
    }

    float lsum = 0.f;
    const uint32_t woff = ((uint32_t)(wid & 3)) << 21;
    const uint32_t chalf = (uint32_t)(wid >> 2);   // column half: 0 -> s 0..63, 1 -> s 64..127

    for (int i = 0; i < NTILES; i++) {
        const int s = i & 1;

        // 1. wait scores for tile i, read both 32-col halves, release S[s]
        MBARRIER_WAIT_PARITY(sb + MB_QK0 + 8 * s, (i >> 1) & 1);
        TCGEN05_FENCE_AFTER();
        uint32_t sr[64];
        LDTM_X32(sr,      tb + 128 * s + chalf * 64);
        LDTM_X32(sr + 32, tb + 128 * s + chalf * 64 + 32);
        TCGEN05_WAIT_LD();
        if (elect_one()) MBARRIER_ARRIVE(sb + MB_SF0 + 8 * s);

        // 2. warp0: issue QK(i+1) into S[s^1]
        if (wid == 0 && (i + 1 < NTILES)) {
            if (elect_one()) {
                if (i >= 1) MBARRIER_WAIT_PARITY(sb + MB_SF0 + 8 * (s ^ 1), ((i - 1) >> 1) & 1);
                MBARRIER_WAIT_PARITY(sb + MB_K0 + 8 * ((i + 1) & 1), ((i + 1) >> 1) & 1);
                const uint32_t kst = sb + SM_KST + (s ^ 1) * 32768;
                const uint64_t kh = mk_desc(kst), kl = mk_desc(kst + 16384);
                const uint32_t dS = tb + 128 * (s ^ 1);
                #pragma unroll
                for (int k = 0; k < 4; k++) mma_ss(dS, aH + 2 * k, kh + 2 * k, IDESC_QK, k != 0);
                #pragma unroll
                for (int k = 0; k < 4; k++) mma_ss(dS, aH + 2 * k, kl + 2 * k, IDESC_QK, true);
                #pragma unroll
                for (int k = 0; k < 4; k++) mma_ss(dS, aL + 2 * k, kh + 2 * k, IDESC_QK, true);
                TCGEN05_COMMIT(sb + MB_QK0 + 8 * (s ^ 1));
            }
        }

        // 3. warp2: prefetch K(i+2) into K-stage s (QK(i) complete, observed in step 1)
        if (wid == 2 && (i + 2 < NTILES)) {
            if (elect_one()) {
                const int j = i + 2;
                const uint32_t kst = sb + SM_KST + s * 32768;
                MBARRIER_EXPECT_TX(sb + MB_K0 + 8 * s, 32768);
                BULK_G2S(kst,         (const char*)g_kt_h + ((size_t)b * 2048 + j * 128) * 128, 16384, sb + MB_K0 + 8 * s);
                BULK_G2S(kst + 16384, (const char*)g_kt_l + ((size_t)b * 2048 + j * 128) * 128, 16384, sb + MB_K0 + 8 * s);
            }
        }

        // 4. softmax in two 32-score halves: exp + split + STTM
        #pragma unroll
        for (int h = 0; h < 2; h++) {
            uint32_t ph[16], pl[16];
            #pragma unroll
            for (int k2 = 0; k2 < 16; k2++) {
                const float p0 = __expf(__uint_as_float(sr[32 * h + 2 * k2]) * 0.125f);
                const float p1 = __expf(__uint_as_float(sr[32 * h + 2 * k2 + 1]) * 0.125f);
                lsum += p0 + p1;
                split2(p0, p1, ph[k2], pl[k2]);
            }
            // P reusable once PV(i-1) finished (wait once, before first STTM)
            if (h == 0 && i >= 1)
                MBARRIER_WAIT_PARITY(sb + MB_PV0 + 8 * ((i - 1) & 1), ((i - 1) >> 1) & 1);
            STTM_X16(tb + TM_PH + chalf * 32 + 16 * h + woff, ph);
            STTM_X16(tb + TM_PL + chalf * 32 + 16 * h + woff, pl);
        }
        TCGEN05_WAIT_ST();
        TCGEN05_FENCE_BEFORE();
        if (elect_one()) MBARRIER_ARRIVE(sb + MB_PR);

        // 5. warp1: issue PV(i) once all 8 P-chunks written (8 k-steps over s)
        if (wid == 1 && elect_one()) {
            MBARRIER_WAIT_PARITY(sb + MB_PR, i & 1);
            TCGEN05_FENCE_AFTER();
            MBARRIER_WAIT_PARITY(sb + MB_V0 + 8 * s, (i >> 1) & 1);
            const uint32_t vst = sb + SM_VST + s * 32768;
            const uint64_t vh = mk_desc(vst), vl = mk_desc(vst + 16384);
            #pragma unroll
            for (int k = 0; k < 8; k++) {
                const uint64_t off = (k < 4) ? (uint64_t)(2 * k) : (uint64_t)(512 + 2 * (k - 4));
                mma_ts(tb + TM_O, tb + TM_PH + 8 * k, vh + off, IDESC_PV, (i > 0) || (k != 0));
            }
            #pragma unroll
            for (int k = 0; k < 8; k++) {
                const uint64_t off = (k < 4) ? (uint64_t)(2 * k) : (uint64_t)(512 + 2 * (k - 4));
                mma_ts(tb + TM_O, tb + TM_PH + 8 * k, vl + off, IDESC_PV, true);
            }
            #pragma unroll
            for (int k = 0; k < 8; k++) {
                const uint64_t off = (k < 4) ? (uint64_t)(2 * k) : (uint64_t)(512 + 2 * (k - 4));
                mma_ts(tb + TM_O, tb + TM_PL + 8 * k, vh + off, IDESC_PV, true);
            }
            TCGEN05_COMMIT(sb + MB_PV0 + 8 * s);
        }

        // 6. warp3: prefetch V(i+1) into V-stage (i+1)&1.
        //    Overwrites V(i-1); guarded by the PV(i-1) wait in step 4.
        if (wid == 3 && (i >= 1) && (i + 1 < NTILES)) {
            if (elect_one()) {
                const int j = i + 1;
                const uint32_t vst = sb + SM_VST + (j & 1) * 32768;
                MBARRIER_EXPECT_TX(sb + MB_V0 + 8 * (j & 1), 32768);
                BULK_G2S(vst,         (const char*)g_v_h + ((size_t)(b * 32 + 2 * j)) * 8192, 16384, sb + MB_V0 + 8 * (j & 1));
                BULK_G2S(vst + 16384, (const char*)g_v_l + ((size_t)(b * 32 + 2 * j)) * 8192, 16384, sb + MB_V0 + 8 * (j & 1));
            }
        }
    }

    // ---- epilogue ----
    *(float*)(smem + SM_LSUM + (wid * 32 + lid) * 4) = lsum;
    __syncthreads();
    {
        MBARRIER_WAIT_PARITY(sb + MB_PV0 + 8 * ((NTILES - 1) & 1), ((NTILES - 1) >> 1) & 1);
        TCGEN05_FENCE_AFTER();
        const float tot = *(float*)(smem + SM_LSUM + (wid * 32 + lid) * 4) +
                          *(float*)(smem + SM_LSUM + (((wid ^ 4) * 32) + lid) * 4);
        const float inv = 1.0f / tot;
        uint32_t o[32];
        LDTM_X32(o, tb + TM_O + chalf * 32);
        TCGEN05_WAIT_LD();
        TCGEN05_FENCE_BEFORE();
        const int row = (wid & 3) * 32 + lid;
        float* op = out + (size_t)b * CH * TT + qb + row;
        const int cbase = (int)chalf * 32;
        #pragma unroll
        for (int c2 = 0; c2 < 32; c2++)
            op[(size_t)(cbase + c2) * TT] = __uint_as_float(o[c2]) * inv;
    }
    __syncthreads();
    if (wid == 0) { TCGEN05_DEALLOC(tb, TM_COLS); }
#endif  // TC_PATH
}

// ---------------- fp32 SIMT fallback (proven: 1781 us) ----------------
#define FBM 64
#define FBN 64
#define FNTH 256
__global__ __launch_bounds__(FNTH) void attn_fp32(const float* __restrict__ qkv,
                                                  float* __restrict__ out) {
    extern __shared__ float smemf[];
    float* sQ = smemf;
    float* sK = smemf + 4096;
    float* sV = smemf + 8192;
    float* sP = smemf + 12288;

    const int b     = blockIdx.y;
    const int qbase = blockIdx.x * FBM;
    const float* qp = qkv + (size_t)b * 3 * CH * TT;
    const float* kp = qp + (size_t)CH * TT;
    const float* vp = qp + (size_t)2 * CH * TT;

    const int tid = threadIdx.x;
    const int tx  = tid & 15;
    const int ty  = tid >> 4;
    const int t0  = ty * 4;
    const int c0  = tx * 4;

    #pragma unroll
    for (int r = ty; r < CH; r += 16) {
        *(float4*)(sQ + r * 64 + tx * 4) =
            *(const float4*)(qp + (size_t)r * TT + qbase + tx * 4);
    }

    float acc[4][4];
    #pragma unroll
    for (int i = 0; i < 4; i++)
        #pragma unroll
        for (int j = 0; j < 4; j++) acc[i][j] = 0.f;
    float mrow[4], lrow[4];
    #pragma unroll
    for (int i = 0; i < 4; i++) { mrow[i] = -1e30f; lrow[i] = 0.f; }

    for (int kt = 0; kt < TT / FBN; ++kt) {
        const int kb = kt * FBN;
        __syncthreads();
        #pragma unroll
        for (int r = ty; r < CH; r += 16) {
            *(float4*)(sK + r * 64 + tx * 4) =
                *(const float4*)(kp + (size_t)r * TT + kb + tx * 4);
            const int scol = (tx * 4) ^ (r & 28);
            *(float4*)(sV + r * 64 + scol) =
                *(const float4*)(vp + (size_t)r * TT + kb + tx * 4);
        }
        __syncthreads();

        float sc[4][4];
        #pragma unroll
        for (int i = 0; i < 4; i++)
            #pragma unroll
            for (int j = 0; j < 4; j++) sc[i][j] = 0.f;

        #pragma unroll 8
        for (int c = 0; c < CH; ++c) {
            float4 qv = *(const float4*)(sQ + c * 64 + t0);
            float4 kv = *(const float4*)(sK + c * 64 + c0);
            const float qa[4] = {qv.x, qv.y, qv.z, qv.w};
            const float ka[4] = {kv.x, kv.y, kv.z, kv.w};
            #pragma unroll
            for (int i = 0; i < 4; i++)
                #pragma unroll
                for (int j = 0; j < 4; j++)
                    sc[i][j] = fmaf(qa[i], ka[j], sc[i][j]);
        }

        #pragma unroll
        for (int i = 0; i < 4; i++) {
            float mx = -1e30f;
            #pragma unroll
            for (int j = 0; j < 4; j++) {
                sc[i][j] *= 0.125f;
                mx = fmaxf(mx, sc[i][j]);
            }
            #pragma unroll
            for (int off = 8; off >= 1; off >>= 1)
                mx = fmaxf(mx, __shfl_xor_sync(0xffffffffu, mx, off));
            const float mnew = fmaxf(mrow[i], mx);
            const float corr = __expf(mrow[i] - mnew);
            float psum = 0.f;
            #pragma unroll
            for (int j = 0; j < 4; j++) {
                const float p = __expf(sc[i][j] - mnew);
                psum += p;
                sP[(t0 + i) * 64 + c0 + j] = p;
            }
            #pragma unroll
            for (int off = 8; off >= 1; off >>= 1)
                psum += __shfl_xor_sync(0xffffffffu, psum, off);
            lrow[i] = lrow[i] * corr + psum;
            mrow[i] = mnew;
            #pragma unroll
            for (int j = 0; j < 4; j++) acc[i][j] *= corr;
        }
        __syncthreads();

        #pragma unroll 4
        for (int s4 = 0; s4 < FBN; s4 += 4) {
            float pv[4][4], vv[4][4];
            #pragma unroll
            for (int i = 0; i < 4; i++)
                *(float4*)pv[i] = *(const float4*)(sP + (t0 + i) * 64 + s4);
            #pragma unroll
            for (int j = 0; j < 4; j++) {
                const int c    = c0 + j;
                const int scol = s4 ^ (c & 28);
                *(float4*)vv[j] = *(const float4*)(sV + c * 64 + scol);
            }
            #pragma unroll
            for (int i = 0; i < 4; i++)
                #pragma unroll
                for (int j = 0; j < 4; j++)
                    #pragma unroll
                    for (int u = 0; u < 4; u++)
                        acc[i][j] = fmaf(pv[i][u], vv[j][u], acc[i][j]);
        }
    }

    float inv[4];
    #pragma unroll
    for (int i = 0; i < 4; i++) inv[i] = 1.0f / lrow[i];
    float* op = out + (size_t)b * CH * TT;
    #pragma unroll
    for (int j = 0; j < 4; j++) {
        float4 o;
        o.x = acc[0][j] * inv[0];
        o.y = acc[1][j] * inv[1];
        o.z = acc[2][j] * inv[2];
        o.w = acc[3][j] * inv[3];
        *(float4*)(op + (size_t)(c0 + j) * TT + qbase + t0) = o;
    }
}

extern "C" void kernel_launch(void* const* d_in, const int* in_sizes, int n_in,
                              void* d_out, int out_size) {
    const float* qkv = (const float*)d_in[0];
    float* out = (float*)d_out;

    cudaFuncAttributes fa{};
    cudaFuncGetAttributes(&fa, attn_tc);
    const bool use_tc = (fa.numRegs >= 40);

    if (use_tc) {
        prep_kernel<<<dim3(32, NB), 256>>>(qkv);
        cudaFuncSetAttribute(attn_tc, cudaFuncAttributeMaxDynamicSharedMemorySize, SM_TOTAL);
        dim3 grid(TT / BM, NB);
        attn_tc<<<grid, NTH, SM_TOTAL>>>(qkv, out);
    } else {
        cudaFuncSetAttribute(attn_fp32, cudaFuncAttributeMaxDynamicSharedMemorySize, 64 * 1024);
        dim3 grid(TT / FBM, NB);
        attn_fp32<<<grid, FNTH, 64 * 1024>>>(qkv, out);
    }
}

// round 12
// speedup vs baseline: 1.4166x; 1.4166x over previous
#include <cuda_runtime.h>
#include <cuda_bf16.h>
#include <cstdint>

#define CH 64
#define TT 2048
#define NB 64
#define BM 128            // queries per CTA
#define BN 64             // keys per iteration
#define NTILES (TT / BN)  // 32
#define NTH 256           // 8 warps
#define NWS 8

// tcgen05 only exists under arch-accelerated targets (sm_103a / sm_100a).
#if defined(__CUDA_ARCH__) && \
    ((__CUDA_ARCH__ == 1030 && defined(__CUDA_ARCH_FEAT_SM103_ALL)) || \
     (__CUDA_ARCH__ == 1000 && defined(__CUDA_ARCH_FEAT_SM100_ALL)))
#define TC_PATH 1
#else
#define TC_PATH 0
#endif

// ---------------- scratch: pre-split, pre-swizzled bf16 tiles (K, V only) ----
__device__ uint32_t g_kt_h[(size_t)NB * 2048 * 32];
__device__ uint32_t g_kt_l[(size_t)NB * 2048 * 32];
__device__ uint32_t g_v_h[(size_t)NB * 32 * 64 * 32];
__device__ uint32_t g_v_l[(size_t)NB * 32 * 64 * 32];

// fast 2-way bf16 split
__device__ __forceinline__ void split2(float f0, float f1, uint32_t& hp, uint32_t& lp) {
    asm("cvt.rn.bf16x2.f32 %0, %1, %2;" : "=r"(hp) : "f"(f1), "f"(f0));
    const float h0 = __uint_as_float(hp << 16);
    const float h1 = __uint_as_float(hp & 0xFFFF0000u);
    asm("cvt.rn.bf16x2.f32 %0, %1, %2;" : "=r"(lp) : "f"(f1 - h1), "f"(f0 - h0));
}

// exp(x*0.125) via single FMUL + ex2  (0.125 * log2(e) = 0.18033688)
__device__ __forceinline__ float exps(float x) {
    float r;
    asm("ex2.approx.ftz.f32 %0, %1;" : "=f"(r) : "f"(x * 0.18033688011112042f));
    return r;
}

// ---------------- prep kernel: fp32 -> split bf16 tiles for K, V -------------
__global__ void prep_kernel(const float* __restrict__ qkv) {
    __shared__ float sT[64 * 65];
    const int b = blockIdx.y, tile = blockIdx.x, t0 = tile * 64;
    const int tid = threadIdx.x;
    const float* qp = qkv + (size_t)b * 3 * CH * TT;
    const float* kp = qp + (size_t)CH * TT;
    const float* vp = qp + 2 * (size_t)CH * TT;

    // V: rows = channel, coalesced both sides
    for (int e = tid; e < 64 * 32; e += 256) {
        const int c = e >> 5, su = e & 31;
        const float2 f = *(const float2*)(vp + (size_t)c * TT + t0 + 2 * su);
        uint32_t hp, lp; split2(f.x, f.y, hp, lp);
        const size_t o = ((size_t)(b * 32 + tile) * 64 + c) * 32 + (su ^ ((c & 7) << 2));
        g_v_h[o] = hp; g_v_l[o] = lp;
    }
    // K transpose via smem
    for (int e = tid; e < 4096; e += 256) {
        const int c = e >> 6, t = e & 63;
        sT[c * 65 + t] = kp[(size_t)c * TT + t0 + t];
    }
    __syncthreads();
    for (int e = tid; e < 2048; e += 256) {
        const int r = e >> 5, un = e & 31;
        uint32_t hp, lp; split2(sT[(2 * un) * 65 + r], sT[(2 * un + 1) * 65 + r], hp, lp);
        const size_t o = ((size_t)b * 2048 + t0 + r) * 32 + (un ^ ((r & 7) << 2));
        g_kt_h[o] = hp; g_kt_l[o] = lp;
    }
}

#if TC_PATH
// ---------------- PTX helpers (sm_103a) ----------------
__device__ __forceinline__ uint32_t smem_u32(const void* p) {
    uint32_t a;
    asm("{ .reg .u64 t; cvta.to.shared.u64 t, %1; cvt.u32.u64 %0, t; }" : "=r"(a) : "l"(p));
    return a;
}
__device__ __forceinline__ uint32_t elect_one() {
    uint32_t p;
    asm volatile("{ .reg .pred p; elect.sync _|p, 0xFFFFFFFF; selp.b32 %0, 1, 0, p; }" : "=r"(p));
    return p;
}

#define MBARRIER_INIT(addr, cnt) \
    asm volatile("mbarrier.init.shared.b64 [%0], %1;" :: "r"((uint32_t)(addr)), "r"((uint32_t)(cnt)) : "memory")
#define MBARRIER_ARRIVE(addr) \
    asm volatile("mbarrier.arrive.shared.b64 _, [%0];" :: "r"((uint32_t)(addr)) : "memory")
#define MBARRIER_EXPECT_TX(addr, n) \
    asm volatile("mbarrier.arrive.expect_tx.shared.b64 _, [%0], %1;" :: "r"((uint32_t)(addr)), "r"((uint32_t)(n)) : "memory")

#define MBARRIER_WAIT_PARITY(addr, par) do {                                             \
    uint32_t _mb = (uint32_t)(addr);  uint32_t _pa = (uint32_t)(par);  uint32_t _dn;     \
    asm volatile("{ .reg .pred p; mbarrier.try_wait.parity.acquire.cta.shared::cta.b64 " \
                 "p, [%1], %2; selp.b32 %0, 1, 0, p; }"                                  \
                 : "=r"(_dn) : "r"(_mb), "r"(_pa) : "memory");                           \
    if (!_dn) {                                                                          \
        asm volatile("{ .reg .pred P1;\n"                                                \
                     "WL_%=: mbarrier.try_wait.parity.acquire.cta.shared::cta.b64 "      \
                     "P1, [%0], %1, 0x989680;\n"                                         \
                     "@P1 bra.uni WD_%=;\n bra.uni WL_%=;\nWD_%=: }"                     \
                     :: "r"(_mb), "r"(_pa) : "memory");                                  \
    } } while (0)

#define BULK_G2S(dst, src, bytes, mbar)                                                          \
    asm volatile("cp.async.bulk.shared::cluster.global.mbarrier::complete_tx::bytes "            \
                 "[%0], [%1], %2, [%3];"                                                          \
                 :: "r"((uint32_t)(dst)), "l"((unsigned long long)(uintptr_t)(src)),              \
                    "r"((uint32_t)(bytes)), "r"((uint32_t)(mbar)) : "memory")

#define TCGEN05_ALLOC(saddr, n) \
    asm volatile("tcgen05.alloc.cta_group::1.sync.aligned.shared::cta.b32 [%0], %1;" \
                 :: "r"((uint32_t)(saddr)), "r"((uint32_t)(n)) : "memory")
#define TCGEN05_DEALLOC(t, n) \
    asm volatile("tcgen05.dealloc.cta_group::1.sync.aligned.b32 %0, %1;" :: "r"(t), "r"((uint32_t)(n)))
#define TCGEN05_RELINQ() \
    asm volatile("tcgen05.relinquish_alloc_permit.cta_group::1.sync.aligned;")
#define TCGEN05_COMMIT(mb) \
    asm volatile("tcgen05.commit.cta_group::1.mbarrier::arrive::one.shared::cluster.b64 [%0];" \
                 :: "r"((uint32_t)(mb)) : "memory")
#define TCGEN05_WAIT_LD()  asm volatile("tcgen05.wait::ld.sync.aligned;" ::: "memory")
#define TCGEN05_WAIT_ST()  asm volatile("tcgen05.wait::st.sync.aligned;" ::: "memory")
#define TCGEN05_FENCE_BEFORE() asm volatile("tcgen05.fence::before_thread_sync;" ::: "memory")
#define TCGEN05_FENCE_AFTER()  asm volatile("tcgen05.fence::after_thread_sync;" ::: "memory")

#define LDTM_X32(r, a)                                                             \
    asm volatile("tcgen05.ld.sync.aligned.32x32b.x32.b32 "                          \
        "{%0,%1,%2,%3,%4,%5,%6,%7,%8,%9,%10,%11,%12,%13,%14,%15,"                  \
        "%16,%17,%18,%19,%20,%21,%22,%23,%24,%25,%26,%27,%28,%29,%30,%31}, [%32];" \
        : "=r"((r)[0]),"=r"((r)[1]),"=r"((r)[2]),"=r"((r)[3]),                      \
          "=r"((r)[4]),"=r"((r)[5]),"=r"((r)[6]),"=r"((r)[7]),                      \
          "=r"((r)[8]),"=r"((r)[9]),"=r"((r)[10]),"=r"((r)[11]),                    \
          "=r"((r)[12]),"=r"((r)[13]),"=r"((r)[14]),"=r"((r)[15]),                  \
          "=r"((r)[16]),"=r"((r)[17]),"=r"((r)[18]),"=r"((r)[19]),                  \
          "=r"((r)[20]),"=r"((r)[21]),"=r"((r)[22]),"=r"((r)[23]),                  \
          "=r"((r)[24]),"=r"((r)[25]),"=r"((r)[26]),"=r"((r)[27]),                  \
          "=r"((r)[28]),"=r"((r)[29]),"=r"((r)[30]),"=r"((r)[31])                   \
        : "r"(a))

#define LDTM_X16(r, a)                                                             \
    asm volatile("tcgen05.ld.sync.aligned.32x32b.x16.b32 "                          \
        "{%0,%1,%2,%3,%4,%5,%6,%7,%8,%9,%10,%11,%12,%13,%14,%15}, [%16];"          \
        : "=r"((r)[0]),"=r"((r)[1]),"=r"((r)[2]),"=r"((r)[3]),                      \
          "=r"((r)[4]),"=r"((r)[5]),"=r"((r)[6]),"=r"((r)[7]),                      \
          "=r"((r)[8]),"=r"((r)[9]),"=r"((r)[10]),"=r"((r)[11]),                    \
          "=r"((r)[12]),"=r"((r)[13]),"=r"((r)[14]),"=r"((r)[15])                   \
        : "r"(a))

#define STTM_X8(a, r)                                                       \
    asm volatile("tcgen05.st.sync.aligned.32x32b.x8.b32 [%0], "             \
        "{%1,%2,%3,%4,%5,%6,%7,%8};"                                        \
        :: "r"(a),                                                          \
           "r"((r)[0]),"r"((r)[1]),"r"((r)[2]),"r"((r)[3]),                 \
           "r"((r)[4]),"r"((r)[5]),"r"((r)[6]),"r"((r)[7])                  \
        : "memory")

static constexpr uint64_t DESC_BASE_SW128 =
    (uint64_t(2) << 61) | (uint64_t(1) << 46) | (uint64_t(64) << 32) | (uint64_t(1) << 16);
__device__ __forceinline__ uint64_t mk_desc(uint32_t a) {
    return DESC_BASE_SW128 | ((uint64_t)(a >> 4) & 0x3FFF);
}

// idesc: F32 accum, BF16 a/b, N=64, M=128 (proven R7-R10)
#define IDESC 0x8100490u

__device__ __forceinline__ void mma_ss(uint32_t d, uint64_t ad, uint64_t bd, bool acc) {
    uint32_t en = acc ? 1u : 0u;
    asm volatile(
        "{ .reg .pred p; setp.ne.u32 p, %5, 0;\n"
        "tcgen05.mma.cta_group::1.kind::f16 [%0], %1, %2, %3, {%4,%4,%4,%4}, p; }"
        :: "r"(d), "l"(ad), "l"(bd), "r"(IDESC), "r"(0u), "r"(en) : "memory");
}
__device__ __forceinline__ void mma_ts(uint32_t d, uint32_t at, uint64_t bd, bool acc) {
    uint32_t en = acc ? 1u : 0u;
    asm volatile(
        "{ .reg .pred p; setp.ne.u32 p, %5, 0;\n"
        "tcgen05.mma.cta_group::1.kind::f16 [%0], [%1], %2, %3, {%4,%4,%4,%4}, p; }"
        :: "r"(d), "r"(at), "l"(bd), "r"(IDESC), "r"(0u), "r"(en) : "memory");
}
#endif  // TC_PATH helpers

// ---------------- SMEM / TMEM layout (tc path) ----------------
#define SM_TPTR   0
#define MB_K0     16
#define MB_K1     24
#define MB_V0     32
#define MB_V1     40
#define MB_QK0    48
#define MB_QK1    56
#define MB_PV0    64
#define MB_PV1    72
#define MB_PR     80
#define MB_SF0    88
#define MB_SF1    96
#define MB_Q      104
#define SM_LSUM   128          // 8*32 floats
#define SM_QH     2048
#define SM_QL     (SM_QH + 16384)
#define SM_KST    (SM_QL + 16384)      // 2 K stages x 16KB; also Q raw staging pre-loop
#define SM_VST    (SM_KST + 32768)     // 2 V stages x 16KB
#define SM_TOTAL  (SM_VST + 32768)     // 100352 bytes

#define TM_PH 128
#define TM_PL 160
#define TM_O  192
#define TM_COLS 256   // S0 @0, S1 @64

// ---------------- tensor-core attention kernel ----------------
__global__ __launch_bounds__(NTH, 2) void attn_tc(const float* __restrict__ qkv,
                                                  float* __restrict__ out) {
#if TC_PATH
    extern __shared__ char smem[];
    const uint32_t sb = smem_u32(smem);
    const int tid = threadIdx.x;
    const int wid = tid >> 5;
    const int lid = tid & 31;
    const int b = blockIdx.y;
    const int qb = blockIdx.x * BM;
    const float* qraw = qkv + (size_t)b * 3 * CH * TT;   // Q base (fp32 [c][t])

    if (wid == 0) { TCGEN05_ALLOC(sb + SM_TPTR, TM_COLS); TCGEN05_RELINQ(); }
    if (tid == 0) {
        MBARRIER_INIT(sb + MB_K0, 1);  MBARRIER_INIT(sb + MB_K1, 1);
        MBARRIER_INIT(sb + MB_V0, 1);  MBARRIER_INIT(sb + MB_V1, 1);
        MBARRIER_INIT(sb + MB_QK0, 1); MBARRIER_INIT(sb + MB_QK1, 1);
        MBARRIER_INIT(sb + MB_PV0, 1); MBARRIER_INIT(sb + MB_PV1, 1);
        MBARRIER_INIT(sb + MB_PR, NWS);
        MBARRIER_INIT(sb + MB_SF0, NWS); MBARRIER_INIT(sb + MB_SF1, NWS);
        MBARRIER_INIT(sb + MB_Q, 1);
    }
    __syncthreads();   // barriers visible before any TMA targets them

    // ---- Q prologue: bulk-load raw fp32 Q rows into padded staging, then
    //      transpose + 2-way bf16 split into QH/QL (SW128). ----
    if (wid == 2 && elect_one()) {
        MBARRIER_EXPECT_TX(sb + MB_Q, 64 * 512);
        for (int c = 0; c < 64; c++)
            BULK_G2S(sb + SM_KST + c * 528, qraw + (size_t)c * TT + qb, 512, sb + MB_Q);
    }
    MBARRIER_WAIT_PARITY(sb + MB_Q, 0);
    {
        const float* stg = (const float*)(smem + SM_KST);   // [c][132] padded
        for (int e = tid; e < 4096; e += NTH) {
            const int un = e >> 7;        // bf16x2 unit (channel pair) 0..31
            const int r  = e & 127;       // query row 0..127
            uint32_t hp, lp;
            split2(stg[(2 * un) * 132 + r], stg[(2 * un + 1) * 132 + r], hp, lp);
            const uint32_t boff = (uint32_t)(r * 128 + ((un * 4) ^ ((r & 7) << 4)));
            *(uint32_t*)(smem + SM_QH + boff) = hp;
            *(uint32_t*)(smem + SM_QL + boff) = lp;
        }
    }
    asm volatile("fence.proxy.async.shared::cta;" ::: "memory");
    __syncthreads();   // staging consumed; K stages may now be overwritten

    uint32_t tb;
    asm volatile("ld.shared.b32 %0, [%1];" : "=r"(tb) : "r"(sb + SM_TPTR));

    const uint64_t aH = mk_desc(sb + SM_QH), aL = mk_desc(sb + SM_QL);

    // Prologue: warp2 loads K0,K1; warp3 loads V0,V1; warp0 issues QK(0).
    if (wid == 2 && elect_one()) {
        #pragma unroll
        for (int j = 0; j < 2; j++) {
            const uint32_t kst = sb + SM_KST + j * 16384;
            MBARRIER_EXPECT_TX(sb + MB_K0 + 8 * j, 16384);
            BULK_G2S(kst,        (const char*)g_kt_h + ((size_t)b * 2048 + j * 64) * 128, 8192, sb + MB_K0 + 8 * j);
            BULK_G2S(kst + 8192, (const char*)g_kt_l + ((size_t)b * 2048 + j * 64) * 128, 8192, sb + MB_K0 + 8 * j);
        }
    }
    if (wid == 3 && elect_one()) {
        #pragma unroll
        for (int j = 0; j < 2; j++) {
            const uint32_t vst = sb + SM_VST + j * 16384;
            MBARRIER_EXPECT_TX(sb + MB_V0 + 8 * j, 16384);
            BULK_G2S(vst,        (const char*)g_v_h + ((size_t)(b * 32 + j)) * 8192, 8192, sb + MB_V0 + 8 * j);
            BULK_G2S(vst + 8192, (const char*)g_v_l + ((size_t)(b * 32 + j)) * 8192, 8192, sb + MB_V0 + 8 * j);
        }
    }
    if (wid == 0 && elect_one()) {
        MBARRIER_WAIT_PARITY(sb + MB_K0, 0);
        const uint32_t kst = sb + SM_KST;
        const uint64_t kh = mk_desc(kst), kl = mk_desc(kst + 8192);
        #pragma unroll
        for (int k = 0; k < 4; k++) mma_ss(tb, aH + 2 * k, kh + 2 * k, k != 0);
        #pragma unroll
        for (int k = 0; k < 4; k++) mma_ss(tb, aH + 2 * k, kl + 2 * k, true);
        #pragma unroll
        for (int k = 0; k < 4; k++) mma_ss(tb, aL + 2 * k, kh + 2 * k, true);
        TCGEN05_COMMIT(sb + MB_QK0);
    }

    float lsum = 0.f;
    const uint32_t woff = ((uint32_t)(wid & 3)) << 21;
    const uint32_t coff = (uint32_t)(wid >> 2) * 16;

    for (int i = 0; i < NTILES; i++) {
        const int s = i & 1;

        // 1. wait scores for tile i
        MBARRIER_WAIT_PARITY(sb + MB_QK0 + 8 * s, (i >> 1) & 1);
        TCGEN05_FENCE_AFTER();
        const uint32_t sbase = tb + 64 * s + (wid >> 2) * 32;

        if (wid == 0) {
            // warp0: unpipelined read so QK(i+1) issues as early as possible
            uint32_t sr[32];
            LDTM_X16(sr, sbase);
            LDTM_X16(sr + 16, sbase + 16);
            TCGEN05_WAIT_LD();
            if (elect_one()) MBARRIER_ARRIVE(sb + MB_SF0 + 8 * s);

            // 2. issue QK(i+1) into S[s^1]
            if ((i + 1 < NTILES) && elect_one()) {
                if (i >= 1) MBARRIER_WAIT_PARITY(sb + MB_SF0 + 8 * (s ^ 1), ((i - 1) >> 1) & 1);
                MBARRIER_WAIT_PARITY(sb + MB_K0 + 8 * ((i + 1) & 1), ((i + 1) >> 1) & 1);
                const uint32_t kst = sb + SM_KST + (s ^ 1) * 16384;
                const uint64_t kh = mk_desc(kst), kl = mk_desc(kst + 8192);
                const uint32_t dS = tb + 64 * (s ^ 1);
                #pragma unroll
                for (int k = 0; k < 4; k++) mma_ss(dS, aH + 2 * k, kh + 2 * k, k != 0);
                #pragma unroll
                for (int k = 0; k < 4; k++) mma_ss(dS, aH + 2 * k, kl + 2 * k, true);
                #pragma unroll
                for (int k = 0; k < 4; k++) mma_ss(dS, aL + 2 * k, kh + 2 * k, true);
                TCGEN05_COMMIT(sb + MB_QK0 + 8 * (s ^ 1));
            }

            uint32_t ph[8], pl[8];
            #pragma unroll
            for (int k2 = 0; k2 < 8; k2++) {
                const float p0 = exps(__uint_as_float(sr[2 * k2]));
                const float p1 = exps(__uint_as_float(sr[2 * k2 + 1]));
                lsum += p0 + p1;
                split2(p0, p1, ph[k2], pl[k2]);
            }
            if (i >= 1) MBARRIER_WAIT_PARITY(sb + MB_PV0 + 8 * ((i - 1) & 1), ((i - 1) >> 1) & 1);
            STTM_X8(tb + TM_PH + coff + woff, ph);
            STTM_X8(tb + TM_PL + coff + woff, pl);
            #pragma unroll
            for (int k2 = 0; k2 < 8; k2++) {
                const float p0 = exps(__uint_as_float(sr[16 + 2 * k2]));
                const float p1 = exps(__uint_as_float(sr[16 + 2 * k2 + 1]));
                lsum += p0 + p1;
                split2(p0, p1, ph[k2], pl[k2]);
            }
            STTM_X8(tb + TM_PH + coff + 8 + woff, ph);
            STTM_X8(tb + TM_PL + coff + 8 + woff, pl);
        } else {
            // warps 1-7: software-pipelined LDTM/exp chunks
            uint32_t sr[16], sr2[16], ph[8], pl[8];
            LDTM_X16(sr, sbase);
            TCGEN05_WAIT_LD();
            LDTM_X16(sr2, sbase + 16);        // drains under chunk-0 exp
            #pragma unroll
            for (int k2 = 0; k2 < 8; k2++) {
                const float p0 = exps(__uint_as_float(sr[2 * k2]));
                const float p1 = exps(__uint_as_float(sr[2 * k2 + 1]));
                lsum += p0 + p1;
                split2(p0, p1, ph[k2], pl[k2]);
            }
            // P reusable once PV(i-1) finished (also guards warp3's V(i+1) prefetch)
            if (i >= 1) MBARRIER_WAIT_PARITY(sb + MB_PV0 + 8 * ((i - 1) & 1), ((i - 1) >> 1) & 1);
            STTM_X8(tb + TM_PH + coff + woff, ph);
            STTM_X8(tb + TM_PL + coff + woff, pl);
            TCGEN05_WAIT_LD();
            if (elect_one()) MBARRIER_ARRIVE(sb + MB_SF0 + 8 * s);
            #pragma unroll
            for (int k2 = 0; k2 < 8; k2++) {
                const float p0 = exps(__uint_as_float(sr2[2 * k2]));
                const float p1 = exps(__uint_as_float(sr2[2 * k2 + 1]));
                lsum += p0 + p1;
                split2(p0, p1, ph[k2], pl[k2]);
            }
            STTM_X8(tb + TM_PH + coff + 8 + woff, ph);
            STTM_X8(tb + TM_PL + coff + 8 + woff, pl);
        }
        TCGEN05_WAIT_ST();
        TCGEN05_FENCE_BEFORE();
        if (elect_one()) MBARRIER_ARRIVE(sb + MB_PR);

        // warp2: prefetch K(i+2) into K-stage s (QK(i) complete, observed in step 1)
        if (wid == 2 && (i + 2 < NTILES)) {
            if (elect_one()) {
                const int j = i + 2;
                const uint32_t kst = sb + SM_KST + s * 16384;
                MBARRIER_EXPECT_TX(sb + MB_K0 + 8 * s, 16384);
                BULK_G2S(kst,        (const char*)g_kt_h + ((size_t)b * 2048 + j * 64) * 128, 8192, sb + MB_K0 + 8 * s);
                BULK_G2S(kst + 8192, (const char*)g_kt_l + ((size_t)b * 2048 + j * 64) * 128, 8192, sb + MB_K0 + 8 * s);
            }
        }

        // warp1: issue PV(i) once all 8 P-chunks written
        if (wid == 1 && elect_one()) {
            MBARRIER_WAIT_PARITY(sb + MB_PR, i & 1);
            TCGEN05_FENCE_AFTER();
            MBARRIER_WAIT_PARITY(sb + MB_V0 + 8 * s, (i >> 1) & 1);
            const uint32_t vst = sb + SM_VST + s * 16384;
            const uint64_t vh = mk_desc(vst), vl = mk_desc(vst + 8192);
            #pragma unroll
            for (int k = 0; k < 4; k++) mma_ts(tb + TM_O, tb + TM_PH + 8 * k, vh + 2 * k, (i > 0) || (k != 0));
            #pragma unroll
            for (int k = 0; k < 4; k++) mma_ts(tb + TM_O, tb + TM_PH + 8 * k, vl + 2 * k, true);
            #pragma unroll
            for (int k = 0; k < 4; k++) mma_ts(tb + TM_O, tb + TM_PL + 8 * k, vh + 2 * k, true);
            TCGEN05_COMMIT(sb + MB_PV0 + 8 * s);
        }

        // warp3: prefetch V(i+1) into V-stage (i+1)&1 (guarded by PV(i-1) wait above)
        if (wid == 3 && (i >= 1) && (i + 1 < NTILES)) {
            if (elect_one()) {
                const int j = i + 1;
                const uint32_t vst = sb + SM_VST + (j & 1) * 16384;
                MBARRIER_EXPECT_TX(sb + MB_V0 + 8 * (j & 1), 16384);
                BULK_G2S(vst,        (const char*)g_v_h + ((size_t)(b * 32 + j)) * 8192, 8192, sb + MB_V0 + 8 * (j & 1));
                BULK_G2S(vst + 8192, (const char*)g_v_l + ((size_t)(b * 32 + j)) * 8192, 8192, sb + MB_V0 + 8 * (j & 1));
            }
        }
    }

    // ---- epilogue ----
    *(float*)(smem + SM_LSUM + (wid * 32 + lid) * 4) = lsum;
    __syncthreads();
    {
        MBARRIER_WAIT_PARITY(sb + MB_PV0 + 8 * ((NTILES - 1) & 1), ((NTILES - 1) >> 1) & 1);
        TCGEN05_FENCE_AFTER();
        const float tot = *(float*)(smem + SM_LSUM + (wid * 32 + lid) * 4) +
                          *(float*)(smem + SM_LSUM + (((wid ^ 4) * 32) + lid) * 4);
        const float inv = 1.0f / tot;
        uint32_t o[32];
        LDTM_X32(o, tb + TM_O + (wid >> 2) * 32);
        TCGEN05_WAIT_LD();
        TCGEN05_FENCE_BEFORE();
        const int row = (wid & 3) * 32 + lid;
        float* op = out + (size_t)b * CH * TT + qb + row;
        const int cbase = (wid >> 2) * 32;
        #pragma unroll
        for (int c2 = 0; c2 < 32; c2++)
            op[(size_t)(cbase + c2) * TT] = __uint_as_float(o[c2]) * inv;
    }
    __syncthreads();
    if (wid == 0) { TCGEN05_DEALLOC(tb, TM_COLS); }
#endif  // TC_PATH
}

// ---------------- fp32 SIMT fallback (proven: 1781 us) ----------------
#define FBM 64
#define FBN 64
#define FNTH 256
__global__ __launch_bounds__(FNTH) void attn_fp32(const float* __restrict__ qkv,
                                                  float* __restrict__ out) {
    extern __shared__ float smemf[];
    float* sQ = smemf;
    float* sK = smemf + 4096;
    float* sV = smemf + 8192;
    float* sP = smemf + 12288;

    const int b     = blockIdx.y;
    const int qbase = blockIdx.x * FBM;
    const float* qp = qkv + (size_t)b * 3 * CH * TT;
    const float* kp = qp + (size_t)CH * TT;
    const float* vp = qp + (size_t)2 * CH * TT;

    const int tid = threadIdx.x;
    const int tx  = tid & 15;
    const int ty  = tid >> 4;
    const int t0  = ty * 4;
    const int c0  = tx * 4;

    #pragma unroll
    for (int r = ty; r < CH; r += 16) {
        *(float4*)(sQ + r * 64 + tx * 4) =
            *(const float4*)(qp + (size_t)r * TT + qbase + tx * 4);
    }

    float acc[4][4];
    #pragma unroll
    for (int i = 0; i < 4; i++)
        #pragma unroll
        for (int j = 0; j < 4; j++) acc[i][j] = 0.f;
    float mrow[4], lrow[4];
    #pragma unroll
    for (int i = 0; i < 4; i++) { mrow[i] = -1e30f; lrow[i] = 0.f; }

    for (int kt = 0; kt < TT / FBN; ++kt) {
        const int kb = kt * FBN;
        __syncthreads();
        #pragma unroll
        for (int r = ty; r < CH; r += 16) {
            *(float4*)(sK + r * 64 + tx * 4) =
                *(const float4*)(kp + (size_t)r * TT + kb + tx * 4);
            const int scol = (tx * 4) ^ (r & 28);
            *(float4*)(sV + r * 64 + scol) =
                *(const float4*)(vp + (size_t)r * TT + kb + tx * 4);
        }
        __syncthreads();

        float sc[4][4];
        #pragma unroll
        for (int i = 0; i < 4; i++)
            #pragma unroll
            for (int j = 0; j < 4; j++) sc[i][j] = 0.f;

        #pragma unroll 8
        for (int c = 0; c < CH; ++c) {
            float4 qv = *(const float4*)(sQ + c * 64 + t0);
            float4 kv = *(const float4*)(sK + c * 64 + c0);
            const float qa[4] = {qv.x, qv.y, qv.z, qv.w};
            const float ka[4] = {kv.x, kv.y, kv.z, kv.w};
            #pragma unroll
            for (int i = 0; i < 4; i++)
                #pragma unroll
                for (int j = 0; j < 4; j++)
                    sc[i][j] = fmaf(qa[i], ka[j], sc[i][j]);
        }

        #pragma unroll
        for (int i = 0; i < 4; i++) {
            float mx = -1e30f;
            #pragma unroll
            for (int j = 0; j < 4; j++) {
                sc[i][j] *= 0.125f;
                mx = fmaxf(mx, sc[i][j]);
            }
            #pragma unroll
            for (int off = 8; off >= 1; off >>= 1)
                mx = fmaxf(mx, __shfl_xor_sync(0xffffffffu, mx, off));
            const float mnew = fmaxf(mrow[i], mx);
            const float corr = __expf(mrow[i] - mnew);
            float psum = 0.f;
            #pragma unroll
            for (int j = 0; j < 4; j++) {
                const float p = __expf(sc[i][j] - mnew);
                psum += p;
                sP[(t0 + i) * 64 + c0 + j] = p;
            }
            #pragma unroll
            for (int off = 8; off >= 1; off >>= 1)
                psum += __shfl_xor_sync(0xffffffffu, psum, off);
            lrow[i] = lrow[i] * corr + psum;
            mrow[i] = mnew;
            #pragma unroll
            for (int j = 0; j < 4; j++) acc[i][j] *= corr;
        }
        __syncthreads();

        #pragma unroll 4
        for (int s4 = 0; s4 < FBN; s4 += 4) {
            float pv[4][4], vv[4][4];
            #pragma unroll
            for (int i = 0; i < 4; i++)
                *(float4*)pv[i] = *(const float4*)(sP + (t0 + i) * 64 + s4);
            #pragma unroll
            for (int j = 0; j < 4; j++) {
                const int c    = c0 + j;
                const int scol = s4 ^ (c & 28);
                *(float4*)vv[j] = *(const float4*)(sV + c * 64 + scol);
            }
            #pragma unroll
            for (int i = 0; i < 4; i++)
                #pragma unroll
                for (int j = 0; j < 4; j++)
                    #pragma unroll
                    for (int u = 0; u < 4; u++)
                        acc[i][j] = fmaf(pv[i][u], vv[j][u], acc[i][j]);
        }
    }

    float inv[4];
    #pragma unroll
    for (int i = 0; i < 4; i++) inv[i] = 1.0f / lrow[i];
    float* op = out + (size_t)b * CH * TT;
    #pragma unroll
    for (int j = 0; j < 4; j++) {
        float4 o;
        o.x = acc[0][j] * inv[0];
        o.y = acc[1][j] * inv[1];
        o.z = acc[2][j] * inv[2];
        o.w = acc[3][j] * inv[3];
        *(float4*)(op + (size_t)(c0 + j) * TT + qbase + t0) = o;
    }
}

extern "C" void kernel_launch(void* const* d_in, const int* in_sizes, int n_in,
                              void* d_out, int out_size) {
    const float* qkv = (const float*)d_in[0];
    float* out = (float*)d_out;

    cudaFuncAttributes fa{};
    cudaFuncGetAttributes(&fa, attn_tc);
    const bool use_tc = (fa.numRegs >= 40);

    if (use_tc) {
        prep_kernel<<<dim3(32, NB), 256>>>(qkv);
        cudaFuncSetAttribute(attn_tc, cudaFuncAttributeMaxDynamicSharedMemorySize, SM_TOTAL);
        dim3 grid(TT / BM, NB);
        attn_tc<<<grid, NTH, SM_TOTAL>>>(qkv, out);
    } else {
        cudaFuncSetAttribute(attn_fp32, cudaFuncAttributeMaxDynamicSharedMemorySize, 64 * 1024);
        dim3 grid(TT / FBM, NB);
        attn_fp32<<<grid, FNTH, 64 * 1024>>>(qkv, out);
    }
}

// round 14
// speedup vs baseline: 1.4451x; 1.0202x over previous
#include <cuda_runtime.h>
#include <cuda_bf16.h>
#include <cstdint>

#define CH 64
#define TT 2048
#define NB 64
#define BM 128            // queries per CTA
#define BN 64             // keys per iteration
#define NTILES (TT / BN)  // 32
#define NTH 256           // 8 warps
#define NWS 8

// tcgen05 only exists under arch-accelerated targets (sm_103a / sm_100a).
#if defined(__CUDA_ARCH__) && \
    ((__CUDA_ARCH__ == 1030 && defined(__CUDA_ARCH_FEAT_SM103_ALL)) || \
     (__CUDA_ARCH__ == 1000 && defined(__CUDA_ARCH_FEAT_SM100_ALL)))
#define TC_PATH 1
#else
#define TC_PATH 0
#endif

// ---------------- scratch: pre-split, pre-swizzled bf16 tiles (K, V only) ----
__device__ uint32_t g_kt_h[(size_t)NB * 2048 * 32];
__device__ uint32_t g_kt_l[(size_t)NB * 2048 * 32];
__device__ uint32_t g_v_h[(size_t)NB * 32 * 64 * 32];
__device__ uint32_t g_v_l[(size_t)NB * 32 * 64 * 32];

// fast 2-way bf16 split
__device__ __forceinline__ void split2(float f0, float f1, uint32_t& hp, uint32_t& lp) {
    asm("cvt.rn.bf16x2.f32 %0, %1, %2;" : "=r"(hp) : "f"(f1), "f"(f0));
    const float h0 = __uint_as_float(hp << 16);
    const float h1 = __uint_as_float(hp & 0xFFFF0000u);
    asm("cvt.rn.bf16x2.f32 %0, %1, %2;" : "=r"(lp) : "f"(f1 - h1), "f"(f0 - h0));
}

// bare ex2 — softmax scale (0.125*log2e) is pre-folded into Q
__device__ __forceinline__ float exps(float y) {
    float r;
    asm("ex2.approx.ftz.f32 %0, %1;" : "=f"(r) : "f"(y));
    return r;
}

// ---------------- prep kernel: fp32 -> split bf16 tiles for K, V -------------
__global__ void prep_kernel(const float* __restrict__ qkv) {
    __shared__ float sT[64 * 65];
    const int b = blockIdx.y, tile = blockIdx.x, t0 = tile * 64;
    const int tid = threadIdx.x;
    const float* qp = qkv + (size_t)b * 3 * CH * TT;
    const float* kp = qp + (size_t)CH * TT;
    const float* vp = qp + 2 * (size_t)CH * TT;

    // V: rows = channel, coalesced both sides
    for (int e = tid; e < 64 * 32; e += 256) {
        const int c = e >> 5, su = e & 31;
        const float2 f = *(const float2*)(vp + (size_t)c * TT + t0 + 2 * su);
        uint32_t hp, lp; split2(f.x, f.y, hp, lp);
        const size_t o = ((size_t)(b * 32 + tile) * 64 + c) * 32 + (su ^ ((c & 7) << 2));
        g_v_h[o] = hp; g_v_l[o] = lp;
    }
    // K transpose via smem
    for (int e = tid; e < 4096; e += 256) {
        const int c = e >> 6, t = e & 63;
        sT[c * 65 + t] = kp[(size_t)c * TT + t0 + t];
    }
    __syncthreads();
    for (int e = tid; e < 2048; e += 256) {
        const int r = e >> 5, un = e & 31;
        uint32_t hp, lp; split2(sT[(2 * un) * 65 + r], sT[(2 * un + 1) * 65 + r], hp, lp);
        const size_t o = ((size_t)b * 2048 + t0 + r) * 32 + (un ^ ((r & 7) << 2));
        g_kt_h[o] = hp; g_kt_l[o] = lp;
    }
}

#if TC_PATH
// ---------------- PTX helpers (sm_103a) ----------------
__device__ __forceinline__ uint32_t smem_u32(const void* p) {
    uint32_t a;
    asm("{ .reg .u64 t; cvta.to.shared.u64 t, %1; cvt.u32.u64 %0, t; }" : "=r"(a) : "l"(p));
    return a;
}
__device__ __forceinline__ uint32_t elect_one() {
    uint32_t p;
    asm volatile("{ .reg .pred p; elect.sync _|p, 0xFFFFFFFF; selp.b32 %0, 1, 0, p; }" : "=r"(p));
    return p;
}

#define MBARRIER_INIT(addr, cnt) \
    asm volatile("mbarrier.init.shared.b64 [%0], %1;" :: "r"((uint32_t)(addr)), "r"((uint32_t)(cnt)) : "memory")
#define MBARRIER_ARRIVE(addr) \
    asm volatile("mbarrier.arrive.shared.b64 _, [%0];" :: "r"((uint32_t)(addr)) : "memory")
#define MBARRIER_EXPECT_TX(addr, n) \
    asm volatile("mbarrier.arrive.expect_tx.shared.b64 _, [%0], %1;" :: "r"((uint32_t)(addr)), "r"((uint32_t)(n)) : "memory")

#define MBARRIER_WAIT_PARITY(addr, par) do {                                             \
    uint32_t _mb = (uint32_t)(addr);  uint32_t _pa = (uint32_t)(par);  uint32_t _dn;     \
    asm volatile("{ .reg .pred p; mbarrier.try_wait.parity.acquire.cta.shared::cta.b64 " \
                 "p, [%1], %2; selp.b32 %0, 1, 0, p; }"                                  \
                 : "=r"(_dn) : "r"(_mb), "r"(_pa) : "memory");                           \
    if (!_dn) {                                                                          \
        asm volatile("{ .reg .pred P1;\n"                                                \
                     "WL_%=: mbarrier.try_wait.parity.acquire.cta.shared::cta.b64 "      \
                     "P1, [%0], %1, 0x989680;\n"                                         \
                     "@P1 bra.uni WD_%=;\n bra.uni WL_%=;\nWD_%=: }"                     \
                     :: "r"(_mb), "r"(_pa) : "memory");                                  \
    } } while (0)

#define BULK_G2S(dst, src, bytes, mbar)                                                          \
    asm volatile("cp.async.bulk.shared::cluster.global.mbarrier::complete_tx::bytes "            \
                 "[%0], [%1], %2, [%3];"                                                          \
                 :: "r"((uint32_t)(dst)), "l"((unsigned long long)(uintptr_t)(src)),              \
                    "r"((uint32_t)(bytes)), "r"((uint32_t)(mbar)) : "memory")

#define TCGEN05_ALLOC(saddr, n) \
    asm volatile("tcgen05.alloc.cta_group::1.sync.aligned.shared::cta.b32 [%0], %1;" \
                 :: "r"((uint32_t)(saddr)), "r"((uint32_t)(n)) : "memory")
#define TCGEN05_DEALLOC(t, n) \
    asm volatile("tcgen05.dealloc.cta_group::1.sync.aligned.b32 %0, %1;" :: "r"(t), "r"((uint32_t)(n)))
#define TCGEN05_RELINQ() \
    asm volatile("tcgen05.relinquish_alloc_permit.cta_group::1.sync.aligned;")
#define TCGEN05_COMMIT(mb) \
    asm volatile("tcgen05.commit.cta_group::1.mbarrier::arrive::one.shared::cluster.b64 [%0];" \
                 :: "r"((uint32_t)(mb)) : "memory")
#define TCGEN05_WAIT_LD()  asm volatile("tcgen05.wait::ld.sync.aligned;" ::: "memory")
#define TCGEN05_WAIT_ST()  asm volatile("tcgen05.wait::st.sync.aligned;" ::: "memory")
#define TCGEN05_FENCE_BEFORE() asm volatile("tcgen05.fence::before_thread_sync;" ::: "memory")
#define TCGEN05_FENCE_AFTER()  asm volatile("tcgen05.fence::after_thread_sync;" ::: "memory")

#define LDTM_X32(r, a)                                                             \
    asm volatile("tcgen05.ld.sync.aligned.32x32b.x32.b32 "                          \
        "{%0,%1,%2,%3,%4,%5,%6,%7,%8,%9,%10,%11,%12,%13,%14,%15,"                  \
        "%16,%17,%18,%19,%20,%21,%22,%23,%24,%25,%26,%27,%28,%29,%30,%31}, [%32];" \
        : "=r"((r)[0]),"=r"((r)[1]),"=r"((r)[2]),"=r"((r)[3]),                      \
          "=r"((r)[4]),"=r"((r)[5]),"=r"((r)[6]),"=r"((r)[7]),                      \
          "=r"((r)[8]),"=r"((r)[9]),"=r"((r)[10]),"=r"((r)[11]),                    \
          "=r"((r)[12]),"=r"((r)[13]),"=r"((r)[14]),"=r"((r)[15]),                  \
          "=r"((r)[16]),"=r"((r)[17]),"=r"((r)[18]),"=r"((r)[19]),                  \
          "=r"((r)[20]),"=r"((r)[21]),"=r"((r)[22]),"=r"((r)[23]),                  \
          "=r"((r)[24]),"=r"((r)[25]),"=r"((r)[26]),"=r"((r)[27]),                  \
          "=r"((r)[28]),"=r"((r)[29]),"=r"((r)[30]),"=r"((r)[31])                   \
        : "r"(a))

#define LDTM_X16(r, a)                                                             \
    asm volatile("tcgen05.ld.sync.aligned.32x32b.x16.b32 "                          \
        "{%0,%1,%2,%3,%4,%5,%6,%7,%8,%9,%10,%11,%12,%13,%14,%15}, [%16];"          \
        : "=r"((r)[0]),"=r"((r)[1]),"=r"((r)[2]),"=r"((r)[3]),                      \
          "=r"((r)[4]),"=r"((r)[5]),"=r"((r)[6]),"=r"((r)[7]),                      \
          "=r"((r)[8]),"=r"((r)[9]),"=r"((r)[10]),"=r"((r)[11]),                    \
          "=r"((r)[12]),"=r"((r)[13]),"=r"((r)[14]),"=r"((r)[15])                   \
        : "r"(a))

#define STTM_X8(a, r)                                                       \
    asm volatile("tcgen05.st.sync.aligned.32x32b.x8.b32 [%0], "             \
        "{%1,%2,%3,%4,%5,%6,%7,%8};"                                        \
        :: "r"(a),                                                          \
           "r"((r)[0]),"r"((r)[1]),"r"((r)[2]),"r"((r)[3]),                 \
           "r"((r)[4]),"r"((r)[5]),"r"((r)[6]),"r"((r)[7])                  \
        : "memory")

static constexpr uint64_t DESC_BASE_SW128 =
    (uint64_t(2) << 61) | (uint64_t(1) << 46) | (uint64_t(64) << 32) | (uint64_t(1) << 16);
__device__ __forceinline__ uint64_t mk_desc(uint32_t a) {
    return DESC_BASE_SW128 | ((uint64_t)(a >> 4) & 0x3FFF);
}

// idesc: F32 accum, BF16 a/b, N=64, M=128 (proven R7-R12)
#define IDESC 0x8100490u

__device__ __forceinline__ void mma_ss(uint32_t d, uint64_t ad, uint64_t bd, bool acc) {
    uint32_t en = acc ? 1u : 0u;
    asm volatile(
        "{ .reg .pred p; setp.ne.u32 p, %5, 0;\n"
        "tcgen05.mma.cta_group::1.kind::f16 [%0], %1, %2, %3, {%4,%4,%4,%4}, p; }"
        :: "r"(d), "l"(ad), "l"(bd), "r"(IDESC), "r"(0u), "r"(en) : "memory");
}
__device__ __forceinline__ void mma_ts(uint32_t d, uint32_t at, uint64_t bd, bool acc) {
    uint32_t en = acc ? 1u : 0u;
    asm volatile(
        "{ .reg .pred p; setp.ne.u32 p, %5, 0;\n"
        "tcgen05.mma.cta_group::1.kind::f16 [%0], [%1], %2, %3, {%4,%4,%4,%4}, p; }"
        :: "r"(d), "r"(at), "l"(bd), "r"(IDESC), "r"(0u), "r"(en) : "memory");
}
#endif  // TC_PATH helpers

// ---------------- SMEM / TMEM layout (tc path) ----------------
#define SM_TPTR   0
#define MB_K0     16
#define MB_K1     24
#define MB_V0     32
#define MB_V1     40
#define MB_QK0    48
#define MB_QK1    56
#define MB_PV0    64
#define MB_PV1    72
#define MB_SF0    88
#define MB_SF1    96
#define MB_Q      104
#define SM_LSUM   128          // 8*32 floats
#define SM_CNT    1536         // 32 iteration counters (128 B)
#define SM_QH     2048
#define SM_QL     (SM_QH + 16384)
#define SM_KST    (SM_QL + 16384)      // 2 K stages x 16KB; also Q raw staging pre-loop
#define SM_VST    (SM_KST + 32768)     // 2 V stages x 16KB
#define SM_TOTAL  (SM_VST + 32768)     // 100352 bytes

#define TM_PH 128
#define TM_PL 160
#define TM_O  192
#define TM_COLS 256   // S0 @0, S1 @64

// ---------------- tensor-core attention kernel ----------------
__global__ __launch_bounds__(NTH, 2) void attn_tc(const float* __restrict__ qkv,
                                                  float* __restrict__ out) {
#if TC_PATH
    extern __shared__ char smem[];
    const uint32_t sb = smem_u32(smem);
    const int tid = threadIdx.x;
    const int wid = tid >> 5;
    const int lid = tid & 31;
    const int b = blockIdx.y;
    const int qb = blockIdx.x * BM;
    const float* qraw = qkv + (size_t)b * 3 * CH * TT;   // Q base (fp32 [c][t])

    if (wid == 0) { TCGEN05_ALLOC(sb + SM_TPTR, TM_COLS); TCGEN05_RELINQ(); }
    if (tid == 0) {
        MBARRIER_INIT(sb + MB_K0, 1);  MBARRIER_INIT(sb + MB_K1, 1);
        MBARRIER_INIT(sb + MB_V0, 1);  MBARRIER_INIT(sb + MB_V1, 1);
        MBARRIER_INIT(sb + MB_QK0, 1); MBARRIER_INIT(sb + MB_QK1, 1);
        MBARRIER_INIT(sb + MB_PV0, 1); MBARRIER_INIT(sb + MB_PV1, 1);
        MBARRIER_INIT(sb + MB_SF0, NWS); MBARRIER_INIT(sb + MB_SF1, NWS);
        MBARRIER_INIT(sb + MB_Q, 1);
    }
    if (tid < NTILES) *(uint32_t*)(smem + SM_CNT + 4 * tid) = 0u;   // PV counters
    __syncthreads();   // barriers + counters visible before use

    // ---- Q prologue: bulk-load raw fp32 Q rows into padded staging, then
    //      transpose + scale-fold (0.125*log2e) + 2-way bf16 split into QH/QL. ----
    if (wid == 2 && elect_one()) {
        MBARRIER_EXPECT_TX(sb + MB_Q, 64 * 512);
        for (int c = 0; c < 64; c++)
            BULK_G2S(sb + SM_KST + c * 528, qraw + (size_t)c * TT + qb, 512, sb + MB_Q);
    }
    MBARRIER_WAIT_PARITY(sb + MB_Q, 0);
    {
        const float SC = 0.18033688011112042f;   // 0.125 * log2(e)
        const float* stg = (const float*)(smem + SM_KST);   // [c][132] padded
        for (int e = tid; e < 4096; e += NTH) {
            const int un = e >> 7;        // bf16x2 unit (channel pair) 0..31
            const int r  = e & 127;       // query row 0..127
            uint32_t hp, lp;
            split2(stg[(2 * un) * 132 + r] * SC, stg[(2 * un + 1) * 132 + r] * SC, hp, lp);
            const uint32_t boff = (uint32_t)(r * 128 + ((un * 4) ^ ((r & 7) << 4)));
            *(uint32_t*)(smem + SM_QH + boff) = hp;
            *(uint32_t*)(smem + SM_QL + boff) = lp;
        }
    }
    asm volatile("fence.proxy.async.shared::cta;" ::: "memory");
    __syncthreads();   // staging consumed; K stages may now be overwritten

    uint32_t tb;
    asm volatile("ld.shared.b32 %0, [%1];" : "=r"(tb) : "r"(sb + SM_TPTR));

    const uint64_t aH = mk_desc(sb + SM_QH), aL = mk_desc(sb + SM_QL);

    // Prologue: warp2 loads K0,K1; warp3 loads V0,V1; warp0 issues QK(0).
    if (wid == 2 && elect_one()) {
        #pragma unroll
        for (int j = 0; j < 2; j++) {
            const uint32_t kst = sb + SM_KST + j * 16384;
            MBARRIER_EXPECT_TX(sb + MB_K0 + 8 * j, 16384);
            BULK_G2S(kst,        (const char*)g_kt_h + ((size_t)b * 2048 + j * 64) * 128, 8192, sb + MB_K0 + 8 * j);
            BULK_G2S(kst + 8192, (const char*)g_kt_l + ((size_t)b * 2048 + j * 64) * 128, 8192, sb + MB_K0 + 8 * j);
        }
    }
    if (wid == 3 && elect_one()) {
        #pragma unroll
        for (int j = 0; j < 2; j++) {
            const uint32_t vst = sb + SM_VST + j * 16384;
            MBARRIER_EXPECT_TX(sb + MB_V0 + 8 * j, 16384);
            BULK_G2S(vst,        (const char*)g_v_h + ((size_t)(b * 32 + j)) * 8192, 8192, sb + MB_V0 + 8 * j);
            BULK_G2S(vst + 8192, (const char*)g_v_l + ((size_t)(b * 32 + j)) * 8192, 8192, sb + MB_V0 + 8 * j);
        }
    }
    if (wid == 0 && elect_one()) {
        MBARRIER_WAIT_PARITY(sb + MB_K0, 0);
        const uint32_t kst = sb + SM_KST;
        const uint64_t kh = mk_desc(kst), kl = mk_desc(kst + 8192);
        #pragma unroll
        for (int k = 0; k < 4; k++) mma_ss(tb, aH + 2 * k, kh + 2 * k, k != 0);
        #pragma unroll
        for (int k = 0; k < 4; k++) mma_ss(tb, aH + 2 * k, kl + 2 * k, true);
        #pragma unroll
        for (int k = 0; k < 4; k++) mma_ss(tb, aL + 2 * k, kh + 2 * k, true);
        TCGEN05_COMMIT(sb + MB_QK0);
    }

    float lsum = 0.f;
    const uint32_t woff = ((uint32_t)(wid & 3)) << 21;
    const uint32_t coff = (uint32_t)(wid >> 2) * 16;

    for (int i = 0; i < NTILES; i++) {
        const int s = i & 1;

        // 1. wait scores for tile i
        MBARRIER_WAIT_PARITY(sb + MB_QK0 + 8 * s, (i >> 1) & 1);
        TCGEN05_FENCE_AFTER();
        const uint32_t sbase = tb + 64 * s + (wid >> 2) * 32;

        if (wid == 0) {
            // warp0: unpipelined read so QK(i+1) issues as early as possible
            uint32_t sr[32];
            LDTM_X16(sr, sbase);
            LDTM_X16(sr + 16, sbase + 16);
            TCGEN05_WAIT_LD();
            if (elect_one()) MBARRIER_ARRIVE(sb + MB_SF0 + 8 * s);

            // 2. issue QK(i+1) into S[s^1]
            if ((i + 1 < NTILES) && elect_one()) {
                if (i >= 1) MBARRIER_WAIT_PARITY(sb + MB_SF0 + 8 * (s ^ 1), ((i - 1) >> 1) & 1);
                MBARRIER_WAIT_PARITY(sb + MB_K0 + 8 * ((i + 1) & 1), ((i + 1) >> 1) & 1);
                const uint32_t kst = sb + SM_KST + (s ^ 1) * 16384;
                const uint64_t kh = mk_desc(kst), kl = mk_desc(kst + 8192);
                const uint32_t dS = tb + 64 * (s ^ 1);
                #pragma unroll
                for (int k = 0; k < 4; k++) mma_ss(dS, aH + 2 * k, kh + 2 * k, k != 0);
                #pragma unroll
                for (int k = 0; k < 4; k++) mma_ss(dS, aH + 2 * k, kl + 2 * k, true);
                #pragma unroll
                for (int k = 0; k < 4; k++) mma_ss(dS, aL + 2 * k, kh + 2 * k, true);
                TCGEN05_COMMIT(sb + MB_QK0 + 8 * (s ^ 1));
            }

            uint32_t ph[8], pl[8];
            #pragma unroll
            for (int k2 = 0; k2 < 8; k2++) {
                const float p0 = exps(__uint_as_float(sr[2 * k2]));
                const float p1 = exps(__uint_as_float(sr[2 * k2 + 1]));
                lsum += p0 + p1;
                split2(p0, p1, ph[k2], pl[k2]);
            }
            if (i >= 1) MBARRIER_WAIT_PARITY(sb + MB_PV0 + 8 * ((i - 1) & 1), ((i - 1) >> 1) & 1);
            STTM_X8(tb + TM_PH + coff + woff, ph);
            STTM_X8(tb + TM_PL + coff + woff, pl);
            #pragma unroll
            for (int k2 = 0; k2 < 8; k2++) {
                const float p0 = exps(__uint_as_float(sr[16 + 2 * k2]));
                const float p1 = exps(__uint_as_float(sr[16 + 2 * k2 + 1]));
                lsum += p0 + p1;
                split2(p0, p1, ph[k2], pl[k2]);
            }
            STTM_X8(tb + TM_PH + coff + 8 + woff, ph);
            STTM_X8(tb + TM_PL + coff + 8 + woff, pl);
        } else {
            // warps 1-7: software-pipelined LDTM/exp chunks
            uint32_t sr[16], sr2[16], ph[8], pl[8];
            LDTM_X16(sr, sbase);
            TCGEN05_WAIT_LD();
            LDTM_X16(sr2, sbase + 16);        // drains under chunk-0 exp
            #pragma unroll
            for (int k2 = 0; k2 < 8; k2++) {
                const float p0 = exps(__uint_as_float(sr[2 * k2]));
                const float p1 = exps(__uint_as_float(sr[2 * k2 + 1]));
                lsum += p0 + p1;
                split2(p0, p1, ph[k2], pl[k2]);
            }
            // P reusable once PV(i-1) finished (also guards warp3's V(i+1) prefetch)
            if (i >= 1) MBARRIER_WAIT_PARITY(sb + MB_PV0 + 8 * ((i - 1) & 1), ((i - 1) >> 1) & 1);
            STTM_X8(tb + TM_PH + coff + woff, ph);
            STTM_X8(tb + TM_PL + coff + woff, pl);
            TCGEN05_WAIT_LD();
            if (elect_one()) MBARRIER_ARRIVE(sb + MB_SF0 + 8 * s);
            #pragma unroll
            for (int k2 = 0; k2 < 8; k2++) {
                const float p0 = exps(__uint_as_float(sr2[2 * k2]));
                const float p1 = exps(__uint_as_float(sr2[2 * k2 + 1]));
                lsum += p0 + p1;
                split2(p0, p1, ph[k2], pl[k2]);
            }
            STTM_X8(tb + TM_PH + coff + 8 + woff, ph);
            STTM_X8(tb + TM_PL + coff + 8 + woff, pl);
        }
        TCGEN05_WAIT_ST();
        TCGEN05_FENCE_BEFORE();

        // Last-arriver issues PV(i): acq_rel counter replaces PR barrier + warp1 hop.
        if (elect_one()) {
            uint32_t old;
            asm volatile("atom.acq_rel.cta.shared.add.u32 %0, [%1], 1;"
                         : "=r"(old) : "r"(sb + SM_CNT + 4 * i) : "memory");
            if (old == NWS - 1) {
                TCGEN05_FENCE_AFTER();
                MBARRIER_WAIT_PARITY(sb + MB_V0 + 8 * s, (i >> 1) & 1);
                const uint32_t vst = sb + SM_VST + s * 16384;
                const uint64_t vh = mk_desc(vst), vl = mk_desc(vst + 8192);
                #pragma unroll
                for (int k = 0; k < 4; k++) mma_ts(tb + TM_O, tb + TM_PH + 8 * k, vh + 2 * k, (i > 0) || (k != 0));
                #pragma unroll
                for (int k = 0; k < 4; k++) mma_ts(tb + TM_O, tb + TM_PH + 8 * k, vl + 2 * k, true);
                #pragma unroll
                for (int k = 0; k < 4; k++) mma_ts(tb + TM_O, tb + TM_PL + 8 * k, vh + 2 * k, true);
                TCGEN05_COMMIT(sb + MB_PV0 + 8 * s);
            }
        }

        // warp2: prefetch K(i+2) into K-stage s (QK(i) complete, observed in step 1)
        if (wid == 2 && (i + 2 < NTILES)) {
            if (elect_one()) {
                const int j = i + 2;
                const uint32_t kst = sb + SM_KST + s * 16384;
                MBARRIER_EXPECT_TX(sb + MB_K0 + 8 * s, 16384);
                BULK_G2S(kst,        (const char*)g_kt_h + ((size_t)b * 2048 + j * 64) * 128, 8192, sb + MB_K0 + 8 * s);
                BULK_G2S(kst + 8192, (const char*)g_kt_l + ((size_t)b * 2048 + j * 64) * 128, 8192, sb + MB_K0 + 8 * s);
            }
        }

        // warp3: prefetch V(i+1) into V-stage (i+1)&1 (guarded by PV(i-1) wait above)
        if (wid == 3 && (i >= 1) && (i + 1 < NTILES)) {
            if (elect_one()) {
                const int j = i + 1;
                const uint32_t vst = sb + SM_VST + (j & 1) * 16384;
                MBARRIER_EXPECT_TX(sb + MB_V0 + 8 * (j & 1), 16384);
                BULK_G2S(vst,        (const char*)g_v_h + ((size_t)(b * 32 + j)) * 8192, 8192, sb + MB_V0 + 8 * (j & 1));
                BULK_G2S(vst + 8192, (const char*)g_v_l + ((size_t)(b * 32 + j)) * 8192, 8192, sb + MB_V0 + 8 * (j & 1));
            }
        }
    }

    // ---- epilogue ----
    *(float*)(smem + SM_LSUM + (wid * 32 + lid) * 4) = lsum;
    __syncthreads();
    {
        MBARRIER_WAIT_PARITY(sb + MB_PV0 + 8 * ((NTILES - 1) & 1), ((NTILES - 1) >> 1) & 1);
        TCGEN05_FENCE_AFTER();
        const float tot = *(float*)(smem + SM_LSUM + (wid * 32 + lid) * 4) +
                          *(float*)(smem + SM_LSUM + (((wid ^ 4) * 32) + lid) * 4);
        const float inv = 1.0f / tot;
        uint32_t o[32];
        LDTM_X32(o, tb + TM_O + (wid >> 2) * 32);
        TCGEN05_WAIT_LD();
        TCGEN05_FENCE_BEFORE();
        const int row = (wid & 3) * 32 + lid;
        float* op = out + (size_t)b * CH * TT + qb + row;
        const int cbase = (wid >> 2) * 32;
        #pragma unroll
        for (int c2 = 0; c2 < 32; c2++)
            op[(size_t)(cbase + c2) * TT] = __uint_as_float(o[c2]) * inv;
    }
    __syncthreads();
    if (wid == 0) { TCGEN05_DEALLOC(tb, TM_COLS); }
#endif  // TC_PATH
}

// ---------------- fp32 SIMT fallback (proven: 1781 us) ----------------
#define FBM 64
#define FBN 64
#define FNTH 256
__global__ __launch_bounds__(FNTH) void attn_fp32(const float* __restrict__ qkv,
                                                  float* __restrict__ out) {
    extern __shared__ float smemf[];
    float* sQ = smemf;
    float* sK = smemf + 4096;
    float* sV = smemf + 8192;
    float* sP = smemf + 12288;

    const int b     = blockIdx.y;
    const int qbase = blockIdx.x * FBM;
    const float* qp = qkv + (size_t)b * 3 * CH * TT;
    const float* kp = qp + (size_t)CH * TT;
    const float* vp = qp + (size_t)2 * CH * TT;

    const int tid = threadIdx.x;
    const int tx  = tid & 15;
    const int ty  = tid >> 4;
    const int t0  = ty * 4;
    const int c0  = tx * 4;

    #pragma unroll
    for (int r = ty; r < CH; r += 16) {
        *(float4*)(sQ + r * 64 + tx * 4) =
            *(const float4*)(qp + (size_t)r * TT + qbase + tx * 4);
    }

    float acc[4][4];
    #pragma unroll
    for (int i = 0; i < 4; i++)
        #pragma unroll
        for (int j = 0; j < 4; j++) acc[i][j] = 0.f;
    float mrow[4], lrow[4];
    #pragma unroll
    for (int i = 0; i < 4; i++) { mrow[i] = -1e30f; lrow[i] = 0.f; }

    for (int kt = 0; kt < TT / FBN; ++kt) {
        const int kb = kt * FBN;
        __syncthreads();
        #pragma unroll
        for (int r = ty; r < CH; r += 16) {
            *(float4*)(sK + r * 64 + tx * 4) =
                *(const float4*)(kp + (size_t)r * TT + kb + tx * 4);
            const int scol = (tx * 4) ^ (r & 28);
            *(float4*)(sV + r * 64 + scol) =
                *(const float4*)(vp + (size_t)r * TT + kb + tx * 4);
        }
        __syncthreads();

        float sc[4][4];
        #pragma unroll
        for (int i = 0; i < 4; i++)
            #pragma unroll
            for (int j = 0; j < 4; j++) sc[i][j] = 0.f;

        #pragma unroll 8
        for (int c = 0; c < CH; ++c) {
            float4 qv = *(const float4*)(sQ + c * 64 + t0);
            float4 kv = *(const float4*)(sK + c * 64 + c0);
            const float qa[4] = {qv.x, qv.y, qv.z, qv.w};
            const float ka[4] = {kv.x, kv.y, kv.z, kv.w};
            #pragma unroll
            for (int i = 0; i < 4; i++)
                #pragma unroll
                for (int j = 0; j < 4; j++)
                    sc[i][j] = fmaf(qa[i], ka[j], sc[i][j]);
        }

        #pragma unroll
        for (int i = 0; i < 4; i++) {
            float mx = -1e30f;
            #pragma unroll
            for (int j = 0; j < 4; j++) {
                sc[i][j] *= 0.125f;
                mx = fmaxf(mx, sc[i][j]);
            }
            #pragma unroll
            for (int off = 8; off >= 1; off >>= 1)
                mx = fmaxf(mx, __shfl_xor_sync(0xffffffffu, mx, off));
            const float mnew = fmaxf(mrow[i], mx);
            const float corr = __expf(mrow[i] - mnew);
            float psum = 0.f;
            #pragma unroll
            for (int j = 0; j < 4; j++) {
                const float p = __expf(sc[i][j] - mnew);
                psum += p;
                sP[(t0 + i) * 64 + c0 + j] = p;
            }
            #pragma unroll
            for (int off = 8; off >= 1; off >>= 1)
                psum += __shfl_xor_sync(0xffffffffu, psum, off);
            lrow[i] = lrow[i] * corr + psum;
            mrow[i] = mnew;
            #pragma unroll
            for (int j = 0; j < 4; j++) acc[i][j] *= corr;
        }
        __syncthreads();

        #pragma unroll 4
        for (int s4 = 0; s4 < FBN; s4 += 4) {
            float pv[4][4], vv[4][4];
            #pragma unroll
            for (int i = 0; i < 4; i++)
                *(float4*)pv[i] = *(const float4*)(sP + (t0 + i) * 64 + s4);
            #pragma unroll
            for (int j = 0; j < 4; j++) {
                const int c    = c0 + j;
                const int scol = s4 ^ (c & 28);
                *(float4*)vv[j] = *(const float4*)(sV + c * 64 + scol);
            }
            #pragma unroll
            for (int i = 0; i < 4; i++)
                #pragma unroll
                for (int j = 0; j < 4; j++)
                    #pragma unroll
                    for (int u = 0; u < 4; u++)
                        acc[i][j] = fmaf(pv[i][u], vv[j][u], acc[i][j]);
        }
    }

    float inv[4];
    #pragma unroll
    for (int i = 0; i < 4; i++) inv[i] = 1.0f / lrow[i];
    float* op = out + (size_t)b * CH * TT;
    #pragma unroll
    for (int j = 0; j < 4; j++) {
        float4 o;
        o.x = acc[0][j] * inv[0];
        o.y = acc[1][j] * inv[1];
        o.z = acc[2][j] * inv[2];
        o.w = acc[3][j] * inv[3];
        *(float4*)(op + (size_t)(c0 + j) * TT + qbase + t0) = o;
    }
}

extern "C" void kernel_launch(void* const* d_in, const int* in_sizes, int n_in,
                              void* d_out, int out_size) {
    const float* qkv = (const float*)d_in[0];
    float* out = (float*)d_out;

    cudaFuncAttributes fa{};
    cudaFuncGetAttributes(&fa, attn_tc);
    const bool use_tc = (fa.numRegs >= 40);

    if (use_tc) {
        prep_kernel<<<dim3(32, NB), 256>>>(qkv);
        cudaFuncSetAttribute(attn_tc, cudaFuncAttributeMaxDynamicSharedMemorySize, SM_TOTAL);
        dim3 grid(TT / BM, NB);
        attn_tc<<<grid, NTH, SM_TOTAL>>>(qkv, out);
    } else {
        cudaFuncSetAttribute(attn_fp32, cudaFuncAttributeMaxDynamicSharedMemorySize, 64 * 1024);
        dim3 grid(TT / FBM, NB);
        attn_fp32<<<grid, FNTH, 64 * 1024>>>(qkv, out);
    }
}

// round 16
// speedup vs baseline: 1.6230x; 1.1231x over previous
#include <cuda_runtime.h>
#include <cuda_bf16.h>
#include <cstdint>

#define CH 64
#define TT 2048
#define NB 64
#define BM 128            // queries per CTA
#define BN 64             // keys per iteration
#define NTILES (TT / BN)  // 32
#define NTH 256           // 8 warps
#define NWS 8

// tcgen05 only exists under arch-accelerated targets (sm_103a / sm_100a).
#if defined(__CUDA_ARCH__) && \
    ((__CUDA_ARCH__ == 1030 && defined(__CUDA_ARCH_FEAT_SM103_ALL)) || \
     (__CUDA_ARCH__ == 1000 && defined(__CUDA_ARCH_FEAT_SM100_ALL)))
#define TC_PATH 1
#else
#define TC_PATH 0
#endif

// ---------------- scratch ----------------
// kt: 2-way bf16 split (hi/lo), SW128-swizzled, [b][t][32 words]
// v:  single fp16, SW128-swizzled, [b][tile64][c(64)][32 words]
__device__ uint32_t g_kt_h[(size_t)NB * 2048 * 32];
__device__ uint32_t g_kt_l[(size_t)NB * 2048 * 32];
__device__ uint32_t g_v_f[(size_t)NB * 32 * 64 * 32];

// fast 2-way bf16 split (Q/K path)
__device__ __forceinline__ void split2(float f0, float f1, uint32_t& hp, uint32_t& lp) {
    asm("cvt.rn.bf16x2.f32 %0, %1, %2;" : "=r"(hp) : "f"(f1), "f"(f0));
    const float h0 = __uint_as_float(hp << 16);
    const float h1 = __uint_as_float(hp & 0xFFFF0000u);
    asm("cvt.rn.bf16x2.f32 %0, %1, %2;" : "=r"(lp) : "f"(f1 - h1), "f"(f0 - h0));
}
// single fp16x2 pack (P/V path)
__device__ __forceinline__ uint32_t packf16(float f0, float f1) {
    uint32_t r;
    asm("cvt.rn.f16x2.f32 %0, %1, %2;" : "=r"(r) : "f"(f1), "f"(f0));
    return r;
}

// bare ex2 — softmax scale (0.125*log2e) is pre-folded into Q
__device__ __forceinline__ float exps(float y) {
    float r;
    asm("ex2.approx.ftz.f32 %0, %1;" : "=f"(r) : "f"(y));
    return r;
}

// ---------------- prep kernel: K -> split bf16, V -> fp16 (runs once) --------
__global__ void prep_kernel(const float* __restrict__ qkv) {
    __shared__ float sT[64 * 65];
    const int b = blockIdx.y, tile = blockIdx.x, t0 = tile * 64;
    const int tid = threadIdx.x;
    const float* qp = qkv + (size_t)b * 3 * CH * TT;
    const float* kp = qp + (size_t)CH * TT;
    const float* vp = qp + 2 * (size_t)CH * TT;

    // V: rows = channel, coalesced both sides, single fp16
    for (int e = tid; e < 64 * 32; e += 256) {
        const int c = e >> 5, su = e & 31;
        const float2 f = *(const float2*)(vp + (size_t)c * TT + t0 + 2 * su);
        const size_t o = ((size_t)(b * 32 + tile) * 64 + c) * 32 + (su ^ ((c & 7) << 2));
        g_v_f[o] = packf16(f.x, f.y);
    }
    // K transpose via smem
    for (int e = tid; e < 4096; e += 256) {
        const int c = e >> 6, t = e & 63;
        sT[c * 65 + t] = kp[(size_t)c * TT + t0 + t];
    }
    __syncthreads();
    for (int e = tid; e < 2048; e += 256) {
        const int r = e >> 5, un = e & 31;
        uint32_t hp, lp; split2(sT[(2 * un) * 65 + r], sT[(2 * un + 1) * 65 + r], hp, lp);
        const size_t o = ((size_t)b * 2048 + t0 + r) * 32 + (un ^ ((r & 7) << 2));
        g_kt_h[o] = hp; g_kt_l[o] = lp;
    }
}

#if TC_PATH
// ---------------- PTX helpers (sm_103a) ----------------
__device__ __forceinline__ uint32_t smem_u32(const void* p) {
    uint32_t a;
    asm("{ .reg .u64 t; cvta.to.shared.u64 t, %1; cvt.u32.u64 %0, t; }" : "=r"(a) : "l"(p));
    return a;
}
__device__ __forceinline__ uint32_t elect_one() {
    uint32_t p;
    asm volatile("{ .reg .pred p; elect.sync _|p, 0xFFFFFFFF; selp.b32 %0, 1, 0, p; }" : "=r"(p));
    return p;
}

#define MBARRIER_INIT(addr, cnt) \
    asm volatile("mbarrier.init.shared.b64 [%0], %1;" :: "r"((uint32_t)(addr)), "r"((uint32_t)(cnt)) : "memory")
#define MBARRIER_ARRIVE(addr) \
    asm volatile("mbarrier.arrive.shared.b64 _, [%0];" :: "r"((uint32_t)(addr)) : "memory")
#define MBARRIER_EXPECT_TX(addr, n) \
    asm volatile("mbarrier.arrive.expect_tx.shared.b64 _, [%0], %1;" :: "r"((uint32_t)(addr)), "r"((uint32_t)(n)) : "memory")

#define MBARRIER_WAIT_PARITY(addr, par) do {                                             \
    uint32_t _mb = (uint32_t)(addr);  uint32_t _pa = (uint32_t)(par);  uint32_t _dn;     \
    asm volatile("{ .reg .pred p; mbarrier.try_wait.parity.acquire.cta.shared::cta.b64 " \
                 "p, [%1], %2; selp.b32 %0, 1, 0, p; }"                                  \
                 : "=r"(_dn) : "r"(_mb), "r"(_pa) : "memory");                           \
    if (!_dn) {                                                                          \
        asm volatile("{ .reg .pred P1;\n"                                                \
                     "WL_%=: mbarrier.try_wait.parity.acquire.cta.shared::cta.b64 "      \
                     "P1, [%0], %1, 0x989680;\n"                                         \
                     "@P1 bra.uni WD_%=;\n bra.uni WL_%=;\nWD_%=: }"                     \
                     :: "r"(_mb), "r"(_pa) : "memory");                                  \
    } } while (0)

#define BULK_G2S(dst, src, bytes, mbar)                                                          \
    asm volatile("cp.async.bulk.shared::cluster.global.mbarrier::complete_tx::bytes "            \
                 "[%0], [%1], %2, [%3];"                                                          \
                 :: "r"((uint32_t)(dst)), "l"((unsigned long long)(uintptr_t)(src)),              \
                    "r"((uint32_t)(bytes)), "r"((uint32_t)(mbar)) : "memory")

#define TCGEN05_ALLOC(saddr, n) \
    asm volatile("tcgen05.alloc.cta_group::1.sync.aligned.shared::cta.b32 [%0], %1;" \
                 :: "r"((uint32_t)(saddr)), "r"((uint32_t)(n)) : "memory")
#define TCGEN05_DEALLOC(t, n) \
    asm volatile("tcgen05.dealloc.cta_group::1.sync.aligned.b32 %0, %1;" :: "r"(t), "r"((uint32_t)(n)))
#define TCGEN05_RELINQ() \
    asm volatile("tcgen05.relinquish_alloc_permit.cta_group::1.sync.aligned;")
#define TCGEN05_COMMIT(mb) \
    asm volatile("tcgen05.commit.cta_group::1.mbarrier::arrive::one.shared::cluster.b64 [%0];" \
                 :: "r"((uint32_t)(mb)) : "memory")
#define TCGEN05_WAIT_LD()  asm volatile("tcgen05.wait::ld.sync.aligned;" ::: "memory")
#define TCGEN05_WAIT_ST()  asm volatile("tcgen05.wait::st.sync.aligned;" ::: "memory")
#define TCGEN05_FENCE_BEFORE() asm volatile("tcgen05.fence::before_thread_sync;" ::: "memory")
#define TCGEN05_FENCE_AFTER()  asm volatile("tcgen05.fence::after_thread_sync;" ::: "memory")

#define LDTM_X32(r, a)                                                             \
    asm volatile("tcgen05.ld.sync.aligned.32x32b.x32.b32 "                          \
        "{%0,%1,%2,%3,%4,%5,%6,%7,%8,%9,%10,%11,%12,%13,%14,%15,"                  \
        "%16,%17,%18,%19,%20,%21,%22,%23,%24,%25,%26,%27,%28,%29,%30,%31}, [%32];" \
        : "=r"((r)[0]),"=r"((r)[1]),"=r"((r)[2]),"=r"((r)[3]),                      \
          "=r"((r)[4]),"=r"((r)[5]),"=r"((r)[6]),"=r"((r)[7]),                      \
          "=r"((r)[8]),"=r"((r)[9]),"=r"((r)[10]),"=r"((r)[11]),                    \
          "=r"((r)[12]),"=r"((r)[13]),"=r"((r)[14]),"=r"((r)[15]),                  \
          "=r"((r)[16]),"=r"((r)[17]),"=r"((r)[18]),"=r"((r)[19]),                  \
          "=r"((r)[20]),"=r"((r)[21]),"=r"((r)[22]),"=r"((r)[23]),                  \
          "=r"((r)[24]),"=r"((r)[25]),"=r"((r)[26]),"=r"((r)[27]),                  \
          "=r"((r)[28]),"=r"((r)[29]),"=r"((r)[30]),"=r"((r)[31])                   \
        : "r"(a))

#define LDTM_X16(r, a)                                                             \
    asm volatile("tcgen05.ld.sync.aligned.32x32b.x16.b32 "                          \
        "{%0,%1,%2,%3,%4,%5,%6,%7,%8,%9,%10,%11,%12,%13,%14,%15}, [%16];"          \
        : "=r"((r)[0]),"=r"((r)[1]),"=r"((r)[2]),"=r"((r)[3]),                      \
          "=r"((r)[4]),"=r"((r)[5]),"=r"((r)[6]),"=r"((r)[7]),                      \
          "=r"((r)[8]),"=r"((r)[9]),"=r"((r)[10]),"=r"((r)[11]),                    \
          "=r"((r)[12]),"=r"((r)[13]),"=r"((r)[14]),"=r"((r)[15])                   \
        : "r"(a))

#define STTM_X8(a, r)                                                       \
    asm volatile("tcgen05.st.sync.aligned.32x32b.x8.b32 [%0], "             \
        "{%1,%2,%3,%4,%5,%6,%7,%8};"                                        \
        :: "r"(a),                                                          \
           "r"((r)[0]),"r"((r)[1]),"r"((r)[2]),"r"((r)[3]),                 \
           "r"((r)[4]),"r"((r)[5]),"r"((r)[6]),"r"((r)[7])                  \
        : "memory")

static constexpr uint64_t DESC_BASE_SW128 =
    (uint64_t(2) << 61) | (uint64_t(1) << 46) | (uint64_t(64) << 32) | (uint64_t(1) << 16);
__device__ __forceinline__ uint64_t mk_desc(uint32_t a) {
    return DESC_BASE_SW128 | ((uint64_t)(a >> 4) & 0x3FFF);
}

// idescs: F32 accum, M=128, N=64. QK: BF16 a/b. PV: F16 a/b (atype=btype=0).
#define IDESC_QK 0x8100490u
#define IDESC_PV 0x8100010u

__device__ __forceinline__ void mma_ss(uint32_t d, uint64_t ad, uint64_t bd, bool acc) {
    uint32_t en = acc ? 1u : 0u;
    asm volatile(
        "{ .reg .pred p; setp.ne.u32 p, %5, 0;\n"
        "tcgen05.mma.cta_group::1.kind::f16 [%0], %1, %2, %3, {%4,%4,%4,%4}, p; }"
        :: "r"(d), "l"(ad), "l"(bd), "r"(IDESC_QK), "r"(0u), "r"(en) : "memory");
}
__device__ __forceinline__ void mma_ts(uint32_t d, uint32_t at, uint64_t bd, bool acc) {
    uint32_t en = acc ? 1u : 0u;
    asm volatile(
        "{ .reg .pred p; setp.ne.u32 p, %5, 0;\n"
        "tcgen05.mma.cta_group::1.kind::f16 [%0], [%1], %2, %3, {%4,%4,%4,%4}, p; }"
        :: "r"(d), "r"(at), "l"(bd), "r"(IDESC_PV), "r"(0u), "r"(en) : "memory");
}
#endif  // TC_PATH helpers

// ---------------- SMEM / TMEM layout (tc path) ----------------
#define SM_TPTR   0
#define MB_K0     16
#define MB_K1     24
#define MB_V0     32
#define MB_V1     40
#define MB_QK0    48
#define MB_QK1    56
#define MB_PV0    64
#define MB_PV1    72
#define MB_SF0    88
#define MB_SF1    96
#define MB_Q      104
#define SM_LSUM   128          // 8*32 floats
#define SM_CNT    1536         // 32 iteration counters (128 B)
#define SM_QH     2048
#define SM_QL     (SM_QH + 16384)
#define SM_KST    (SM_QL + 16384)      // 2 K stages x 16KB; also Q raw staging pre-loop
#define SM_VST    (SM_KST + 32768)     // 2 V stages x 8KB (fp16)
#define SM_TOTAL  (SM_VST + 16384)     // 83968 bytes (2 CTAs/SM)

#define TM_P  128   // P: 32 cols fp16x2
#define TM_O  192
#define TM_COLS 256   // S0 @0, S1 @64

// ---------------- tensor-core attention kernel ----------------
__global__ __launch_bounds__(NTH, 2) void attn_tc(const float* __restrict__ qkv,
                                                  float* __restrict__ out) {
#if TC_PATH
    extern __shared__ char smem[];
    const uint32_t sb = smem_u32(smem);
    const int tid = threadIdx.x;
    const int wid = tid >> 5;
    const int lid = tid & 31;
    const int b = blockIdx.y;
    const int qb = blockIdx.x * BM;
    const float* qraw = qkv + (size_t)b * 3 * CH * TT;   // Q base (fp32 [c][t])

    if (wid == 0) { TCGEN05_ALLOC(sb + SM_TPTR, TM_COLS); TCGEN05_RELINQ(); }
    if (tid == 0) {
        MBARRIER_INIT(sb + MB_K0, 1);  MBARRIER_INIT(sb + MB_K1, 1);
        MBARRIER_INIT(sb + MB_V0, 1);  MBARRIER_INIT(sb + MB_V1, 1);
        MBARRIER_INIT(sb + MB_QK0, 1); MBARRIER_INIT(sb + MB_QK1, 1);
        MBARRIER_INIT(sb + MB_PV0, 1); MBARRIER_INIT(sb + MB_PV1, 1);
        MBARRIER_INIT(sb + MB_SF0, NWS); MBARRIER_INIT(sb + MB_SF1, NWS);
        MBARRIER_INIT(sb + MB_Q, 1);
    }
    if (tid < NTILES) *(uint32_t*)(smem + SM_CNT + 4 * tid) = 0u;   // PV counters
    __syncthreads();   // barriers + counters visible before use

    // ---- Q prologue: bulk-load raw fp32 Q rows into padded staging, then
    //      transpose + scale-fold (0.125*log2e) + 2-way bf16 split into QH/QL. ----
    if (wid == 2 && elect_one()) {
        MBARRIER_EXPECT_TX(sb + MB_Q, 64 * 512);
        for (int c = 0; c < 64; c++)
            BULK_G2S(sb + SM_KST + c * 528, qraw + (size_t)c * TT + qb, 512, sb + MB_Q);
    }
    MBARRIER_WAIT_PARITY(sb + MB_Q, 0);
    {
        const float SC = 0.18033688011112042f;   // 0.125 * log2(e)
        const float* stg = (const float*)(smem + SM_KST);   // [c][132] padded
        for (int e = tid; e < 4096; e += NTH) {
            const int un = e >> 7;        // bf16x2 unit (channel pair) 0..31
            const int r  = e & 127;       // query row 0..127
            uint32_t hp, lp;
            split2(stg[(2 * un) * 132 + r] * SC, stg[(2 * un + 1) * 132 + r] * SC, hp, lp);
            const uint32_t boff = (uint32_t)(r * 128 + ((un * 4) ^ ((r & 7) << 4)));
            *(uint32_t*)(smem + SM_QH + boff) = hp;
            *(uint32_t*)(smem + SM_QL + boff) = lp;
        }
    }
    asm volatile("fence.proxy.async.shared::cta;" ::: "memory");
    __syncthreads();   // staging consumed; K/V stages may now be overwritten

    uint32_t tb;
    asm volatile("ld.shared.b32 %0, [%1];" : "=r"(tb) : "r"(sb + SM_TPTR));

    const uint64_t aH = mk_desc(sb + SM_QH), aL = mk_desc(sb + SM_QL);

    // Prologue: warp2 loads K0,K1; warp3 loads V0,V1; warp0 issues QK(0).
    if (wid == 2 && elect_one()) {
        #pragma unroll
        for (int j = 0; j < 2; j++) {
            const uint32_t kst = sb + SM_KST + j * 16384;
            MBARRIER_EXPECT_TX(sb + MB_K0 + 8 * j, 16384);
            BULK_G2S(kst,        (const char*)g_kt_h + ((size_t)b * 2048 + j * 64) * 128, 8192, sb + MB_K0 + 8 * j);
            BULK_G2S(kst + 8192, (const char*)g_kt_l + ((size_t)b * 2048 + j * 64) * 128, 8192, sb + MB_K0 + 8 * j);
        }
    }
    if (wid == 3 && elect_one()) {
        #pragma unroll
        for (int j = 0; j < 2; j++) {
            const uint32_t vst = sb + SM_VST + j * 8192;
            MBARRIER_EXPECT_TX(sb + MB_V0 + 8 * j, 8192);
            BULK_G2S(vst, (const char*)g_v_f + ((size_t)(b * 32 + j)) * 8192, 8192, sb + MB_V0 + 8 * j);
        }
    }
    if (wid == 0 && elect_one()) {
        MBARRIER_WAIT_PARITY(sb + MB_K0, 0);
        const uint32_t kst = sb + SM_KST;
        const uint64_t kh = mk_desc(kst), kl = mk_desc(kst + 8192);
        #pragma unroll
        for (int k = 0; k < 4; k++) mma_ss(tb, aH + 2 * k, kh + 2 * k, k != 0);
        #pragma unroll
        for (int k = 0; k < 4; k++) mma_ss(tb, aH + 2 * k, kl + 2 * k, true);
        #pragma unroll
        for (int k = 0; k < 4; k++) mma_ss(tb, aL + 2 * k, kh + 2 * k, true);
        TCGEN05_COMMIT(sb + MB_QK0);
    }

    float lsum = 0.f;
    const uint32_t woff = ((uint32_t)(wid & 3)) << 21;
    const uint32_t coff = (uint32_t)(wid >> 2) * 16;

    for (int i = 0; i < NTILES; i++) {
        const int s = i & 1;

        // 1. wait scores for tile i
        MBARRIER_WAIT_PARITY(sb + MB_QK0 + 8 * s, (i >> 1) & 1);
        TCGEN05_FENCE_AFTER();
        const uint32_t sbase = tb + 64 * s + (wid >> 2) * 32;

        if (wid == 0) {
            // warp0: unpipelined read so QK(i+1) issues as early as possible
            uint32_t sr[32];
            LDTM_X16(sr, sbase);
            LDTM_X16(sr + 16, sbase + 16);
            TCGEN05_WAIT_LD();
            if (elect_one()) MBARRIER_ARRIVE(sb + MB_SF0 + 8 * s);

            // 2. issue QK(i+1) into S[s^1]
            if ((i + 1 < NTILES) && elect_one()) {
                if (i >= 1) MBARRIER_WAIT_PARITY(sb + MB_SF0 + 8 * (s ^ 1), ((i - 1) >> 1) & 1);
                MBARRIER_WAIT_PARITY(sb + MB_K0 + 8 * ((i + 1) & 1), ((i + 1) >> 1) & 1);
                const uint32_t kst = sb + SM_KST + (s ^ 1) * 16384;
                const uint64_t kh = mk_desc(kst), kl = mk_desc(kst + 8192);
                const uint32_t dS = tb + 64 * (s ^ 1);
                #pragma unroll
                for (int k = 0; k < 4; k++) mma_ss(dS, aH + 2 * k, kh + 2 * k, k != 0);
                #pragma unroll
                for (int k = 0; k < 4; k++) mma_ss(dS, aH + 2 * k, kl + 2 * k, true);
                #pragma unroll
                for (int k = 0; k < 4; k++) mma_ss(dS, aL + 2 * k, kh + 2 * k, true);
                TCGEN05_COMMIT(sb + MB_QK0 + 8 * (s ^ 1));
            }

            uint32_t pp[8];
            #pragma unroll
            for (int k2 = 0; k2 < 8; k2++) {
                const float p0 = exps(__uint_as_float(sr[2 * k2]));
                const float p1 = exps(__uint_as_float(sr[2 * k2 + 1]));
                lsum += p0 + p1;
                pp[k2] = packf16(p0, p1);
            }
            if (i >= 1) MBARRIER_WAIT_PARITY(sb + MB_PV0 + 8 * ((i - 1) & 1), ((i - 1) >> 1) & 1);
            STTM_X8(tb + TM_P + coff + woff, pp);
            #pragma unroll
            for (int k2 = 0; k2 < 8; k2++) {
                const float p0 = exps(__uint_as_float(sr[16 + 2 * k2]));
                const float p1 = exps(__uint_as_float(sr[16 + 2 * k2 + 1]));
                lsum += p0 + p1;
                pp[k2] = packf16(p0, p1);
            }
            STTM_X8(tb + TM_P + coff + 8 + woff, pp);
        } else {
            // warps 1-7: software-pipelined LDTM/exp chunks
            uint32_t sr[16], sr2[16], pp[8];
            LDTM_X16(sr, sbase);
            TCGEN05_WAIT_LD();
            LDTM_X16(sr2, sbase + 16);        // drains under chunk-0 exp
            #pragma unroll
            for (int k2 = 0; k2 < 8; k2++) {
                const float p0 = exps(__uint_as_float(sr[2 * k2]));
                const float p1 = exps(__uint_as_float(sr[2 * k2 + 1]));
                lsum += p0 + p1;
                pp[k2] = packf16(p0, p1);
            }
            // P reusable once PV(i-1) finished (also guards warp3's V(i+1) prefetch)
            if (i >= 1) MBARRIER_WAIT_PARITY(sb + MB_PV0 + 8 * ((i - 1) & 1), ((i - 1) >> 1) & 1);
            STTM_X8(tb + TM_P + coff + woff, pp);
            TCGEN05_WAIT_LD();
            if (elect_one()) MBARRIER_ARRIVE(sb + MB_SF0 + 8 * s);
            #pragma unroll
            for (int k2 = 0; k2 < 8; k2++) {
                const float p0 = exps(__uint_as_float(sr2[2 * k2]));
                const float p1 = exps(__uint_as_float(sr2[2 * k2 + 1]));
                lsum += p0 + p1;
                pp[k2] = packf16(p0, p1);
            }
            STTM_X8(tb + TM_P + coff + 8 + woff, pp);
        }
        TCGEN05_WAIT_ST();
        TCGEN05_FENCE_BEFORE();

        // Last-arriver issues PV(i): acq_rel counter (proven R13/R14 pattern)
        if (elect_one()) {
            uint32_t old;
            asm volatile("atom.acq_rel.cta.shared.add.u32 %0, [%1], 1;"
                         : "=r"(old) : "r"(sb + SM_CNT + 4 * i) : "memory");
            if (old == NWS - 1) {
                TCGEN05_FENCE_AFTER();
                MBARRIER_WAIT_PARITY(sb + MB_V0 + 8 * s, (i >> 1) & 1);
                const uint64_t vd = mk_desc(sb + SM_VST + s * 8192);
                #pragma unroll
                for (int k = 0; k < 4; k++)
                    mma_ts(tb + TM_O, tb + TM_P + 8 * k, vd + 2 * k, (i > 0) || (k != 0));
                TCGEN05_COMMIT(sb + MB_PV0 + 8 * s);
            }
        }

        // warp2: prefetch K(i+2) into K-stage s (QK(i) complete, observed in step 1)
        if (wid == 2 && (i + 2 < NTILES)) {
            if (elect_one()) {
                const int j = i + 2;
                const uint32_t kst = sb + SM_KST + s * 16384;
                MBARRIER_EXPECT_TX(sb + MB_K0 + 8 * s, 16384);
                BULK_G2S(kst,        (const char*)g_kt_h + ((size_t)b * 2048 + j * 64) * 128, 8192, sb + MB_K0 + 8 * s);
                BULK_G2S(kst + 8192, (const char*)g_kt_l + ((size_t)b * 2048 + j * 64) * 128, 8192, sb + MB_K0 + 8 * s);
            }
        }

        // warp3: prefetch V(i+1) into V-stage (i+1)&1 (guarded by PV(i-1) wait above)
        if (wid == 3 && (i >= 1) && (i + 1 < NTILES)) {
            if (elect_one()) {
                const int j = i + 1;
                const uint32_t vst = sb + SM_VST + (j & 1) * 8192;
                MBARRIER_EXPECT_TX(sb + MB_V0 + 8 * (j & 1), 8192);
                BULK_G2S(vst, (const char*)g_v_f + ((size_t)(b * 32 + j)) * 8192, 8192, sb + MB_V0 + 8 * (j & 1));
            }
        }
    }

    // ---- epilogue ----
    *(float*)(smem + SM_LSUM + (wid * 32 + lid) * 4) = lsum;
    __syncthreads();
    {
        MBARRIER_WAIT_PARITY(sb + MB_PV0 + 8 * ((NTILES - 1) & 1), ((NTILES - 1) >> 1) & 1);
        TCGEN05_FENCE_AFTER();
        const float tot = *(float*)(smem + SM_LSUM + (wid * 32 + lid) * 4) +
                          *(float*)(smem + SM_LSUM + (((wid ^ 4) * 32) + lid) * 4);
        const float inv = 1.0f / tot;
        uint32_t o[32];
        LDTM_X32(o, tb + TM_O + (wid >> 2) * 32);
        TCGEN05_WAIT_LD();
        TCGEN05_FENCE_BEFORE();
        const int row = (wid & 3) * 32 + lid;
        float* op = out + (size_t)b * CH * TT + qb + row;
        const int cbase = (wid >> 2) * 32;
        #pragma unroll
        for (int c2 = 0; c2 < 32; c2++)
            op[(size_t)(cbase + c2) * TT] = __uint_as_float(o[c2]) * inv;
    }
    __syncthreads();
    if (wid == 0) { TCGEN05_DEALLOC(tb, TM_COLS); }
#endif  // TC_PATH
}

// ---------------- fp32 SIMT fallback (proven: 1781 us) ----------------
#define FBM 64
#define FBN 64
#define FNTH 256
__global__ __launch_bounds__(FNTH) void attn_fp32(const float* __restrict__ qkv,
                                                  float* __restrict__ out) {
    extern __shared__ float smemf[];
    float* sQ = smemf;
    float* sK = smemf + 4096;
    float* sV = smemf + 8192;
    float* sP = smemf + 12288;

    const int b     = blockIdx.y;
    const int qbase = blockIdx.x * FBM;
    const float* qp = qkv + (size_t)b * 3 * CH * TT;
    const float* kp = qp + (size_t)CH * TT;
    const float* vp = qp + (size_t)2 * CH * TT;

    const int tid = threadIdx.x;
    const int tx  = tid & 15;
    const int ty  = tid >> 4;
    const int t0  = ty * 4;
    const int c0  = tx * 4;

    #pragma unroll
    for (int r = ty; r < CH; r += 16) {
        *(float4*)(sQ + r * 64 + tx * 4) =
            *(const float4*)(qp + (size_t)r * TT + qbase + tx * 4);
    }

    float acc[4][4];
    #pragma unroll
    for (int i = 0; i < 4; i++)
        #pragma unroll
        for (int j = 0; j < 4; j++) acc[i][j] = 0.f;
    float mrow[4], lrow[4];
    #pragma unroll
    for (int i = 0; i < 4; i++) { mrow[i] = -1e30f; lrow[i] = 0.f; }

    for (int kt = 0; kt < TT / FBN; ++kt) {
        const int kb = kt * FBN;
        __syncthreads();
        #pragma unroll
        for (int r = ty; r < CH; r += 16) {
            *(float4*)(sK + r * 64 + tx * 4) =
                *(const float4*)(kp + (size_t)r * TT + kb + tx * 4);
            const int scol = (tx * 4) ^ (r & 28);
            *(float4*)(sV + r * 64 + scol) =
                *(const float4*)(vp + (size_t)r * TT + kb + tx * 4);
        }
        __syncthreads();

        float sc[4][4];
        #pragma unroll
        for (int i = 0; i < 4; i++)
            #pragma unroll
            for (int j = 0; j < 4; j++) sc[i][j] = 0.f;

        #pragma unroll 8
        for (int c = 0; c < CH; ++c) {
            float4 qv = *(const float4*)(sQ + c * 64 + t0);
            float4 kv = *(const float4*)(sK + c * 64 + c0);
            const float qa[4] = {qv.x, qv.y, qv.z, qv.w};
            const float ka[4] = {kv.x, kv.y, kv.z, kv.w};
            #pragma unroll
            for (int i = 0; i < 4; i++)
                #pragma unroll
                for (int j = 0; j < 4; j++)
                    sc[i][j] = fmaf(qa[i], ka[j], sc[i][j]);
        }

        #pragma unroll
        for (int i = 0; i < 4; i++) {
            float mx = -1e30f;
            #pragma unroll
            for (int j = 0; j < 4; j++) {
                sc[i][j] *= 0.125f;
                mx = fmaxf(mx, sc[i][j]);
            }
            #pragma unroll
            for (int off = 8; off >= 1; off >>= 1)
                mx = fmaxf(mx, __shfl_xor_sync(0xffffffffu, mx, off));
            const float mnew = fmaxf(mrow[i], mx);
            const float corr = __expf(mrow[i] - mnew);
            float psum = 0.f;
            #pragma unroll
            for (int j = 0; j < 4; j++) {
                const float p = __expf(sc[i][j] - mnew);
                psum += p;
                sP[(t0 + i) * 64 + c0 + j] = p;
            }
            #pragma unroll
            for (int off = 8; off >= 1; off >>= 1)
                psum += __shfl_xor_sync(0xffffffffu, psum, off);
            lrow[i] = lrow[i] * corr + psum;
            mrow[i] = mnew;
            #pragma unroll
            for (int j = 0; j < 4; j++) acc[i][j] *= corr;
        }
        __syncthreads();

        #pragma unroll 4
        for (int s4 = 0; s4 < FBN; s4 += 4) {
            float pv[4][4], vv[4][4];
            #pragma unroll
            for (int i = 0; i < 4; i++)
                *(float4*)pv[i] = *(const float4*)(sP + (t0 + i) * 64 + s4);
            #pragma unroll
            for (int j = 0; j < 4; j++) {
                const int c    = c0 + j;
                const int scol = s4 ^ (c & 28);
                *(float4*)vv[j] = *(const float4*)(sV + c * 64 + scol);
            }
            #pragma unroll
            for (int i = 0; i < 4; i++)
                #pragma unroll
                for (int j = 0; j < 4; j++)
                    #pragma unroll
                    for (int u = 0; u < 4; u++)
                        acc[i][j] = fmaf(pv[i][u], vv[j][u], acc[i][j]);
        }
    }

    float inv[4];
    #pragma unroll
    for (int i = 0; i < 4; i++) inv[i] = 1.0f / lrow[i];
    float* op = out + (size_t)b * CH * TT;
    #pragma unroll
    for (int j = 0; j < 4; j++) {
        float4 o;
        o.x = acc[0][j] * inv[0];
        o.y = acc[1][j] * inv[1];
        o.z = acc[2][j] * inv[2];
        o.w = acc[3][j] * inv[3];
        *(float4*)(op + (size_t)(c0 + j) * TT + qbase + t0) = o;
    }
}

extern "C" void kernel_launch(void* const* d_in, const int* in_sizes, int n_in,
                              void* d_out, int out_size) {
    const float* qkv = (const float*)d_in[0];
    float* out = (float*)d_out;

    cudaFuncAttributes fa{};
    cudaFuncGetAttributes(&fa, attn_tc);
    const bool use_tc = (fa.numRegs >= 40);

    if (use_tc) {
        prep_kernel<<<dim3(32, NB), 256>>>(qkv);
        cudaFuncSetAttribute(attn_tc, cudaFuncAttributeMaxDynamicSharedMemorySize, SM_TOTAL);
        dim3 grid(TT / BM, NB);
        attn_tc<<<grid, NTH, SM_TOTAL>>>(qkv, out);
    } else {
        cudaFuncSetAttribute(attn_fp32, cudaFuncAttributeMaxDynamicSharedMemorySize, 64 * 1024);
        dim3 grid(TT / FBM, NB);
        attn_fp32<<<grid, FNTH, 64 * 1024>>>(qkv, out);
    }
}